// round 1
// baseline (speedup 1.0000x reference)
#include <cuda_runtime.h>
#include <cuda_bf16.h>
#include <math.h>

// ---------------- problem constants ----------------
#define BB      32
#define CC      3
#define IMG     224
#define NP      14
#define PS      16
#define IN_DIM  768
#define DD      768
#define NH      12
#define DH      64
#define LL      12
#define MLPD    3072
#define OUTC    1000
#define SS      197          // NP*NP + 1
#define NTOK    (BB*SS)      // 6304
#define NPATCH  (BB*NP*NP)   // 6272

// ---------------- scratch (device globals; no runtime alloc) ----------------
static __device__ float g_resid[NTOK*DD];
static __device__ float g_xn[NTOK*DD];
static __device__ float g_patch[NPATCH*IN_DIM];
static __device__ float g_q[NTOK*DD];
static __device__ float g_k[NTOK*DD];
static __device__ float g_v[NTOK*DD];
static __device__ float g_h[NTOK*MLPD];

// ---------------- patchify: gather x into [6272, 768] ----------------
__global__ void patchify_kernel(const float* __restrict__ x, float* __restrict__ patch)
{
    int m = blockIdx.x;                 // 0..6271
    int b = m / (NP*NP);
    int p = m % (NP*NP);
    int py = p / NP, px = p % NP;
    for (int i = threadIdx.x; i < IN_DIM; i += blockDim.x) {
        int c = i >> 8;                 // /256
        int r = (i >> 4) & 15;
        int s = i & 15;
        size_t src = ((size_t)(b*CC + c)*IMG + (py*PS + r))*IMG + (px*PS + s);
        patch[(size_t)m*IN_DIM + i] = x[src];
    }
}

// ---------------- cls token init ----------------
__global__ void cls_init_kernel(const float* __restrict__ cls_emb,
                                const float* __restrict__ pos,
                                float* __restrict__ resid)
{
    int b = blockIdx.x;
    for (int d = threadIdx.x; d < DD; d += blockDim.x)
        resid[(size_t)b*SS*DD + d] = cls_emb[d] + pos[d];
}

// ---------------- SGEMM 128x128x8, 8x8/thread (4x4 quadrants) ----------------
// MODE 0: C = A@B + bias
// MODE 1: C = gelu(A@B + bias)
// MODE 2: C += A@B + bias
// MODE 3: patch-embed epilogue: row remap + bias + pos
template<int MODE>
__global__ void sgemm_kernel(const float* __restrict__ A, const float* __restrict__ Bm,
                             const float* __restrict__ bias, float* __restrict__ C,
                             int M, int N, int K, const float* __restrict__ extra)
{
    __shared__ float As[8*128];
    __shared__ float Bs[8*128];

    const int tid = threadIdx.x;
    const int bx = blockIdx.x, by = blockIdx.y;
    const int tx = tid & 15, ty = tid >> 4;

    float acc[8][8];
#pragma unroll
    for (int i = 0; i < 8; i++)
#pragma unroll
        for (int j = 0; j < 8; j++) acc[i][j] = 0.f;

    const int aRow = tid >> 1;            // 0..127
    const int aK   = (tid & 1) * 4;       // 0 or 4
    const int bK   = tid >> 5;            // 0..7
    const int bCol = (tid & 31) * 4;
    const int globARow = by*128 + aRow;

    for (int k0 = 0; k0 < K; k0 += 8) {
        float4 av;
        if (globARow < M) av = *(const float4*)(A + (size_t)globARow*K + k0 + aK);
        else              av = make_float4(0.f,0.f,0.f,0.f);
        As[(aK+0)*128 + aRow] = av.x;
        As[(aK+1)*128 + aRow] = av.y;
        As[(aK+2)*128 + aRow] = av.z;
        As[(aK+3)*128 + aRow] = av.w;
        float4 bv = *(const float4*)(Bm + (size_t)(k0 + bK)*N + bx*128 + bCol);
        *(float4*)(Bs + bK*128 + bCol) = bv;
        __syncthreads();

#pragma unroll
        for (int kk = 0; kk < 8; kk++) {
            float a[8], b[8];
#pragma unroll
            for (int i = 0; i < 4; i++) {
                a[i]   = As[kk*128 + ty*4 + i];
                a[4+i] = As[kk*128 + 64 + ty*4 + i];
                b[i]   = Bs[kk*128 + tx*4 + i];
                b[4+i] = Bs[kk*128 + 64 + tx*4 + i];
            }
#pragma unroll
            for (int i = 0; i < 8; i++)
#pragma unroll
                for (int j = 0; j < 8; j++)
                    acc[i][j] += a[i]*b[j];
        }
        __syncthreads();
    }

#pragma unroll
    for (int i = 0; i < 8; i++) {
        int r = (i < 4) ? (ty*4 + i) : (64 + ty*4 + (i-4));
        int row = by*128 + r;
        if (row >= M) continue;
#pragma unroll
        for (int j = 0; j < 8; j++) {
            int cc = (j < 4) ? (tx*4 + j) : (64 + tx*4 + (j-4));
            int col = bx*128 + cc;
            float val = acc[i][j] + bias[col];
            if (MODE == 0) {
                C[(size_t)row*N + col] = val;
            } else if (MODE == 1) {
                C[(size_t)row*N + col] = 0.5f*val*(1.f + erff(val*0.70710678118654752f));
            } else if (MODE == 2) {
                C[(size_t)row*N + col] += val;
            } else { // MODE 3: patch embed -> resid rows with pos add
                int bb = row / (NP*NP);
                int pp = row % (NP*NP);
                int orow = bb*SS + 1 + pp;
                C[(size_t)orow*DD + col] = val + extra[(size_t)(pp+1)*DD + col];
            }
        }
    }
}

// ---------------- LayerNorm (one CTA per token row) ----------------
__global__ void ln_kernel(const float* __restrict__ xin, const float* __restrict__ g,
                          const float* __restrict__ bet, float* __restrict__ xout)
{
    int row = blockIdx.x;
    const float* xr = xin + (size_t)row*DD;
    int tid = threadIdx.x;
    float v0 = xr[tid], v1 = xr[tid+256], v2 = xr[tid+512];
    float s  = v0+v1+v2;
    float ss = v0*v0 + v1*v1 + v2*v2;

    __shared__ float rs[8], rss[8], smv[2];
    int lane = tid & 31, w = tid >> 5;
#pragma unroll
    for (int off = 16; off; off >>= 1) {
        s  += __shfl_xor_sync(0xffffffffu, s,  off);
        ss += __shfl_xor_sync(0xffffffffu, ss, off);
    }
    if (lane == 0) { rs[w] = s; rss[w] = ss; }
    __syncthreads();
    if (tid == 0) {
        float S = 0.f, SSq = 0.f;
#pragma unroll
        for (int i = 0; i < 8; i++) { S += rs[i]; SSq += rss[i]; }
        float mean = S * (1.f/768.f);
        float var  = SSq * (1.f/768.f) - mean*mean;
        smv[0] = mean;
        smv[1] = rsqrtf(var + 1e-5f);
    }
    __syncthreads();
    float mean = smv[0], rstd = smv[1];
    float* xo = xout + (size_t)row*DD;
    xo[tid]     = (v0 - mean)*rstd*g[tid]     + bet[tid];
    xo[tid+256] = (v1 - mean)*rstd*g[tid+256] + bet[tid+256];
    xo[tid+512] = (v2 - mean)*rstd*g[tid+512] + bet[tid+512];
}

// ---------------- QKV projection (per-head 64x64) ----------------
// grid (197, 12), block 256, dynamic smem
__global__ void qkv_kernel(const float* __restrict__ xn,
                           const float* __restrict__ Wq, const float* __restrict__ Wk,
                           const float* __restrict__ Wv,
                           const float* __restrict__ bq, const float* __restrict__ bk,
                           const float* __restrict__ bv,
                           float* __restrict__ q, float* __restrict__ k, float* __restrict__ v)
{
    extern __shared__ float sm[];
    float* sW = sm;                 // 3 * 64 * 65
    float* sb = sW + 3*64*65;       // 3 * 64
    float* sx = sb + 192;           // 32 * 64

    const int h = blockIdx.y;
    const int tok0 = blockIdx.x * 32;
    const int tid = threadIdx.x;

    for (int o = tid; o < 3*4096; o += 256) {
        int mat = o >> 12;
        int e = (o >> 6) & 63;
        int d = o & 63;
        const float* W = (mat == 0) ? Wq : (mat == 1) ? Wk : Wv;
        sW[mat*4160 + e*65 + d] = W[(size_t)(h*64 + e)*64 + d];
    }
    if (tid < 192) {
        int mat = tid / 64, e = tid % 64;
        const float* bbp = (mat == 0) ? bq : (mat == 1) ? bk : bv;
        sb[tid] = bbp[h*64 + e];
    }
    for (int o = tid; o < 2048; o += 256) {
        int t = o >> 6, d = o & 63;
        int tok = tok0 + t;
        sx[o] = (tok < NTOK) ? xn[(size_t)tok*DD + h*64 + d] : 0.f;
    }
    __syncthreads();

#pragma unroll
    for (int i = 0; i < 24; i++) {
        int o = i*256 + tid;
        int mat = o >> 11;
        int rem = o & 2047;
        int t = rem >> 6, e = rem & 63;
        int tok = tok0 + t;
        if (tok >= NTOK) continue;
        const float* wrow = &sW[mat*4160 + e*65];
        const float* xrow = &sx[t*64];
        float acc = 0.f;
#pragma unroll
        for (int d = 0; d < 64; d++) acc += xrow[d]*wrow[d];
        acc += sb[mat*64 + e];
        int b = tok / SS, s = tok % SS;
        float* dst = (mat == 0) ? q : (mat == 1) ? k : v;
        dst[(((size_t)b*NH + h)*SS + s)*DH + e] = acc;
    }
}

// ---------------- fused attention (one CTA per (b,h)), residual-add epilogue ----
// grid 384, block 128, dynamic smem ~107KB
__global__ void attn_kernel(const float* __restrict__ q, const float* __restrict__ k,
                            const float* __restrict__ v, float* __restrict__ resid)
{
    extern __shared__ float sm[];
    float* ks = sm;                 // 197*65
    float* vs = ks + 197*65;        // 197*65
    float* qs = vs + 197*65;        // 4*64
    float* ps = qs + 256;           // 4*200

    const int bh = blockIdx.x;
    const int b = bh / NH, h = bh % NH;
    const size_t base = (size_t)bh * SS * DH;
    const int tid = threadIdx.x;
    const int w = tid >> 5, lane = tid & 31;

    for (int idx = tid; idx < SS*DH; idx += 128) {
        int j = idx >> 6, e = idx & 63;
        ks[j*65 + e] = k[base + idx];
        vs[j*65 + e] = v[base + idx];
    }
    __syncthreads();

    for (int s = w; s < SS; s += 4) {
        qs[w*64 + lane]      = q[base + (size_t)s*64 + lane];
        qs[w*64 + 32 + lane] = q[base + (size_t)s*64 + 32 + lane];
        __syncwarp();

        float sc[7];
        float m = -1e30f;
#pragma unroll
        for (int jj = 0; jj < 7; jj++) {
            int j = jj*32 + lane;
            float acc;
            if (j < SS) {
                const float* kr = &ks[j*65];
                const float* qr = &qs[w*64];
                acc = 0.f;
#pragma unroll
                for (int e = 0; e < 64; e++) acc += qr[e]*kr[e];
                acc *= 0.125f;
            } else acc = -1e30f;
            sc[jj] = acc;
            m = fmaxf(m, acc);
        }
#pragma unroll
        for (int off = 16; off; off >>= 1)
            m = fmaxf(m, __shfl_xor_sync(0xffffffffu, m, off));

        float sum = 0.f;
#pragma unroll
        for (int jj = 0; jj < 7; jj++) {
            int j = jj*32 + lane;
            float p = (j < SS) ? __expf(sc[jj] - m) : 0.f;
            sum += p;
            if (j < SS) ps[w*200 + j] = p;
        }
#pragma unroll
        for (int off = 16; off; off >>= 1)
            sum += __shfl_xor_sync(0xffffffffu, sum, off);
        float inv = 1.f / sum;
        __syncwarp();

        float a0 = 0.f, a1 = 0.f;
        for (int j = 0; j < SS; j++) {
            float p = ps[w*200 + j];
            a0 += p * vs[j*65 + lane];
            a1 += p * vs[j*65 + lane + 32];
        }
        size_t ridx = ((size_t)(b*SS + s))*DD + h*DH;
        resid[ridx + lane]      += a0 * inv;
        resid[ridx + 32 + lane] += a1 * inv;
        __syncwarp();
    }
}

// ---------------- classifier head + softmax ----------------
__global__ void head_kernel(const float* __restrict__ resid, const float* __restrict__ Wc,
                            const float* __restrict__ bc, float* __restrict__ out)
{
    __shared__ float sx[768];
    __shared__ float logit[1000];
    __shared__ float red[8];
    __shared__ float bscalar;

    int b = blockIdx.x;
    int tid = threadIdx.x;
    int lane = tid & 31, w = tid >> 5;

    for (int i = tid; i < 768; i += 256) sx[i] = resid[(size_t)b*SS*DD + i];
    __syncthreads();

    for (int o = tid; o < OUTC; o += 256) {
        float acc = bc[o];
        for (int kk = 0; kk < 768; kk++) acc += sx[kk]*Wc[(size_t)kk*OUTC + o];
        logit[o] = acc;
    }
    __syncthreads();

    // max
    float m = -1e30f;
    for (int o = tid; o < OUTC; o += 256) m = fmaxf(m, logit[o]);
#pragma unroll
    for (int off = 16; off; off >>= 1) m = fmaxf(m, __shfl_xor_sync(0xffffffffu, m, off));
    if (lane == 0) red[w] = m;
    __syncthreads();
    if (tid == 0) {
        float mm = red[0];
#pragma unroll
        for (int i = 1; i < 8; i++) mm = fmaxf(mm, red[i]);
        bscalar = mm;
    }
    __syncthreads();
    m = bscalar;

    // sum of exp
    float s = 0.f;
    for (int o = tid; o < OUTC; o += 256) {
        float e = __expf(logit[o] - m);
        logit[o] = e;
        s += e;
    }
#pragma unroll
    for (int off = 16; off; off >>= 1) s += __shfl_xor_sync(0xffffffffu, s, off);
    if (lane == 0) red[w] = s;
    __syncthreads();
    if (tid == 0) {
        float ssum = 0.f;
#pragma unroll
        for (int i = 0; i < 8; i++) ssum += red[i];
        bscalar = 1.f / ssum;
    }
    __syncthreads();
    float invs = bscalar;
    for (int o = tid; o < OUTC; o += 256)
        out[(size_t)b*OUTC + o] = logit[o] * invs;
}

// ---------------- launcher ----------------
extern "C" void kernel_launch(void* const* d_in, const int* in_sizes, int n_in,
                              void* d_out, int out_size)
{
    const float* x       = (const float*)d_in[0];
    const float* cls_emb = (const float*)d_in[1];
    const float* pos     = (const float*)d_in[2];
    const float* Wmap    = (const float*)d_in[3];
    const float* bmap    = (const float*)d_in[4];
    const float* ln1_g   = (const float*)d_in[5];
    const float* ln1_b   = (const float*)d_in[6];
    const float* Wq      = (const float*)d_in[7];
    const float* bq      = (const float*)d_in[8];
    const float* Wk      = (const float*)d_in[9];
    const float* bk      = (const float*)d_in[10];
    const float* Wv      = (const float*)d_in[11];
    const float* bv      = (const float*)d_in[12];
    const float* ln2_g   = (const float*)d_in[13];
    const float* ln2_b   = (const float*)d_in[14];
    const float* W1      = (const float*)d_in[15];
    const float* b1      = (const float*)d_in[16];
    const float* W2      = (const float*)d_in[17];
    const float* b2      = (const float*)d_in[18];
    const float* Wc      = (const float*)d_in[19];
    const float* bc      = (const float*)d_in[20];
    float* out = (float*)d_out;

    float *resid, *xn, *patch, *q, *k, *v, *hbuf;
    cudaGetSymbolAddress((void**)&resid, g_resid);
    cudaGetSymbolAddress((void**)&xn,    g_xn);
    cudaGetSymbolAddress((void**)&patch, g_patch);
    cudaGetSymbolAddress((void**)&q,     g_q);
    cudaGetSymbolAddress((void**)&k,     g_k);
    cudaGetSymbolAddress((void**)&v,     g_v);
    cudaGetSymbolAddress((void**)&hbuf,  g_h);

    const int QKV_SMEM = (3*64*65 + 192 + 2048) * 4;          // 58,880 B
    const int ATT_SMEM = (2*197*65 + 256 + 800) * 4;          // 106,664 B
    cudaFuncSetAttribute(qkv_kernel,  cudaFuncAttributeMaxDynamicSharedMemorySize, QKV_SMEM);
    cudaFuncSetAttribute(attn_kernel, cudaFuncAttributeMaxDynamicSharedMemorySize, ATT_SMEM);

    // patch embed + positional
    patchify_kernel<<<NPATCH, 256>>>(x, patch);
    sgemm_kernel<3><<<dim3(DD/128, NPATCH/128), 256>>>(patch, Wmap, bmap, resid,
                                                       NPATCH, DD, IN_DIM, pos);
    cls_init_kernel<<<BB, 256>>>(cls_emb, pos, resid);

    const int MT = (NTOK + 127) / 128;   // 50
    for (int l = 0; l < LL; l++) {
        ln_kernel<<<NTOK, 256>>>(resid, ln1_g + (size_t)l*DD, ln1_b + (size_t)l*DD, xn);
        qkv_kernel<<<dim3(NTOK/32, NH), 256, QKV_SMEM>>>(
            xn,
            Wq + (size_t)l*NH*DH*DH, Wk + (size_t)l*NH*DH*DH, Wv + (size_t)l*NH*DH*DH,
            bq + (size_t)l*NH*DH,    bk + (size_t)l*NH*DH,    bv + (size_t)l*NH*DH,
            q, k, v);
        attn_kernel<<<BB*NH, 128, ATT_SMEM>>>(q, k, v, resid);

        ln_kernel<<<NTOK, 256>>>(resid, ln2_g + (size_t)l*DD, ln2_b + (size_t)l*DD, xn);
        sgemm_kernel<1><<<dim3(MLPD/128, MT), 256>>>(xn, W1 + (size_t)l*DD*MLPD,
                                                     b1 + (size_t)l*MLPD, hbuf,
                                                     NTOK, MLPD, DD, nullptr);
        sgemm_kernel<2><<<dim3(DD/128, MT), 256>>>(hbuf, W2 + (size_t)l*MLPD*DD,
                                                   b2 + (size_t)l*DD, resid,
                                                   NTOK, DD, MLPD, nullptr);
    }

    head_kernel<<<BB, 256>>>(resid, Wc, bc, out);
}

// round 3
// speedup vs baseline: 1.6609x; 1.6609x over previous
#include <cuda_runtime.h>
#include <cuda_bf16.h>
#include <math.h>
#include <stdint.h>

// ---------------- problem constants ----------------
#define BB      32
#define CC      3
#define IMG     224
#define NP      14
#define PS      16
#define IN_DIM  768
#define DD      768
#define NH      12
#define DH      64
#define LL      12
#define MLPD    3072
#define OUTC    1000
#define SS      197          // NP*NP + 1
#define NTOK    (BB*SS)      // 6304
#define NPATCH  (BB*NP*NP)   // 6272
#define MPAD    6400         // NTOK padded to 50*128

#define KA1     (2*DD)       // 1536: A storage [hi|lo] for GEMM1
#define KB1     (3*DD)       // 2304: B storage [hi|hi|lo]
#define KA2     (2*MLPD)     // 6144
#define KB2     (3*MLPD)     // 9216

// ---------------- scratch (device globals; no runtime alloc) ----------------
static __device__ float g_resid[NTOK*DD];
static __device__ float g_xn[NTOK*DD];
static __device__ float g_patch[NPATCH*IN_DIM];
static __device__ float g_q[NTOK*DD];
static __device__ float g_k[NTOK*DD];
static __device__ float g_v[NTOK*DD];
static __device__ __nv_bfloat16 g_xs[(size_t)MPAD*KA1];     // split ln2 activations
static __device__ __nv_bfloat16 g_hs[(size_t)MPAD*KA2];     // split gelu activations
static __device__ __nv_bfloat16 g_w1p[(size_t)LL*MLPD*KB1]; // W1 transposed+split
static __device__ __nv_bfloat16 g_w2p[(size_t)LL*DD*KB2];   // W2 transposed+split

// ================= arch-generic tensor-core helpers =================
__device__ __forceinline__ uint32_t smem_u32(const void* p) {
    uint32_t a;
    asm("{ .reg .u64 t; cvta.to.shared.u64 t, %1; cvt.u32.u64 %0, t; }" : "=r"(a) : "l"(p));
    return a;
}
__device__ __forceinline__ void cp_async16(uint32_t smem, const void* g) {
    asm volatile("cp.async.cg.shared.global [%0], [%1], 16;" :: "r"(smem), "l"(g));
}
#define CP_COMMIT() asm volatile("cp.async.commit_group;" ::: "memory")
#define CP_WAIT1()  asm volatile("cp.async.wait_group 1;" ::: "memory")
#define CP_WAIT0()  asm volatile("cp.async.wait_group 0;" ::: "memory")

__device__ __forceinline__ void ldmx4(uint32_t* r, uint32_t addr) {
    asm volatile("ldmatrix.sync.aligned.m8n8.x4.shared.b16 {%0,%1,%2,%3}, [%4];"
        : "=r"(r[0]), "=r"(r[1]), "=r"(r[2]), "=r"(r[3]) : "r"(addr));
}
__device__ __forceinline__ void mma16816(float* d, const uint32_t* a, uint32_t b0, uint32_t b1) {
    asm volatile(
        "mma.sync.aligned.m16n8k16.row.col.f32.bf16.bf16.f32 "
        "{%0,%1,%2,%3}, {%4,%5,%6,%7}, {%8,%9}, {%0,%1,%2,%3};"
        : "+f"(d[0]), "+f"(d[1]), "+f"(d[2]), "+f"(d[3])
        : "r"(a[0]), "r"(a[1]), "r"(a[2]), "r"(a[3]), "r"(b0), "r"(b1));
}
__device__ __forceinline__ uint32_t pack_bf2(float x, float y) {
    __nv_bfloat162 t = __floats2bfloat162_rn(x, y);
    return *(uint32_t*)&t;
}

// ---------------- patchify ----------------
__global__ void patchify_kernel(const float* __restrict__ x, float* __restrict__ patch)
{
    int m = blockIdx.x;
    int b = m / (NP*NP);
    int p = m % (NP*NP);
    int py = p / NP, px = p % NP;
    for (int i = threadIdx.x; i < IN_DIM; i += blockDim.x) {
        int c = i >> 8;
        int r = (i >> 4) & 15;
        int s = i & 15;
        size_t src = ((size_t)(b*CC + c)*IMG + (py*PS + r))*IMG + (px*PS + s);
        patch[(size_t)m*IN_DIM + i] = x[src];
    }
}

__global__ void cls_init_kernel(const float* __restrict__ cls_emb,
                                const float* __restrict__ pos,
                                float* __restrict__ resid)
{
    int b = blockIdx.x;
    for (int d = threadIdx.x; d < DD; d += blockDim.x)
        resid[(size_t)b*SS*DD + d] = cls_emb[d] + pos[d];
}

// ---------------- fp32 SGEMM (patch embed only) ----------------
template<int MODE>
__global__ void sgemm_kernel(const float* __restrict__ A, const float* __restrict__ Bm,
                             const float* __restrict__ bias, float* __restrict__ C,
                             int M, int N, int K, const float* __restrict__ extra)
{
    __shared__ float As[8*128];
    __shared__ float Bs[8*128];

    const int tid = threadIdx.x;
    const int bx = blockIdx.x, by = blockIdx.y;
    const int tx = tid & 15, ty = tid >> 4;

    float acc[8][8];
#pragma unroll
    for (int i = 0; i < 8; i++)
#pragma unroll
        for (int j = 0; j < 8; j++) acc[i][j] = 0.f;

    const int aRow = tid >> 1;
    const int aK   = (tid & 1) * 4;
    const int bK   = tid >> 5;
    const int bCol = (tid & 31) * 4;
    const int globARow = by*128 + aRow;

    for (int k0 = 0; k0 < K; k0 += 8) {
        float4 av;
        if (globARow < M) av = *(const float4*)(A + (size_t)globARow*K + k0 + aK);
        else              av = make_float4(0.f,0.f,0.f,0.f);
        As[(aK+0)*128 + aRow] = av.x;
        As[(aK+1)*128 + aRow] = av.y;
        As[(aK+2)*128 + aRow] = av.z;
        As[(aK+3)*128 + aRow] = av.w;
        float4 bv = *(const float4*)(Bm + (size_t)(k0 + bK)*N + bx*128 + bCol);
        *(float4*)(Bs + bK*128 + bCol) = bv;
        __syncthreads();

#pragma unroll
        for (int kk = 0; kk < 8; kk++) {
            float a[8], b[8];
#pragma unroll
            for (int i = 0; i < 4; i++) {
                a[i]   = As[kk*128 + ty*4 + i];
                a[4+i] = As[kk*128 + 64 + ty*4 + i];
                b[i]   = Bs[kk*128 + tx*4 + i];
                b[4+i] = Bs[kk*128 + 64 + tx*4 + i];
            }
#pragma unroll
            for (int i = 0; i < 8; i++)
#pragma unroll
                for (int j = 0; j < 8; j++)
                    acc[i][j] += a[i]*b[j];
        }
        __syncthreads();
    }

#pragma unroll
    for (int i = 0; i < 8; i++) {
        int r = (i < 4) ? (ty*4 + i) : (64 + ty*4 + (i-4));
        int row = by*128 + r;
        if (row >= M) continue;
#pragma unroll
        for (int j = 0; j < 8; j++) {
            int cc = (j < 4) ? (tx*4 + j) : (64 + tx*4 + (j-4));
            int col = bx*128 + cc;
            float val = acc[i][j] + bias[col];
            if (MODE == 0) {
                C[(size_t)row*N + col] = val;
            } else { // MODE 3: patch embed -> resid rows with pos add
                int bb = row / (NP*NP);
                int pp = row % (NP*NP);
                int orow = bb*SS + 1 + pp;
                C[(size_t)orow*DD + col] = val + extra[(size_t)(pp+1)*DD + col];
            }
        }
    }
}

// ---------------- weight prep: transpose + bf16 split, stacked K ----------------
// W: [K, N] fp32 row-major (per layer). Wp: [N, 3K] bf16: [hi | hi | lo]
__global__ void wprep_kernel(const float* __restrict__ W, __nv_bfloat16* __restrict__ Wp,
                             int K, int N)
{
    __shared__ float t[32][33];
    int l = blockIdx.z;
    const float* Wl = W + (size_t)l*K*N;
    __nv_bfloat16* Wpl = Wp + (size_t)l*N*3*K;
    int n0 = blockIdx.x*32, k0 = blockIdx.y*32;
    int tx = threadIdx.x, ty = threadIdx.y;

    t[ty][tx] = Wl[(size_t)(k0+ty)*N + n0+tx];
    __syncthreads();
    float v = t[tx][ty];                     // = W[k0+tx][n0+ty]
    int row = n0+ty, col = k0+tx;
    __nv_bfloat16 hi = __float2bfloat16(v);
    __nv_bfloat16 lo = __float2bfloat16(v - __bfloat162float(hi));
    __nv_bfloat16* dst = Wpl + (size_t)row*3*K;
    dst[col]       = hi;
    dst[K + col]   = hi;
    dst[2*K + col] = lo;
}

// ---------------- LayerNorm ----------------
// SPLIT=0: fp32 xout. SPLIT=1: split bf16 into xs [row, 1536] = [hi|lo]
template<int SPLIT>
__global__ void ln_kernel(const float* __restrict__ xin, const float* __restrict__ g,
                          const float* __restrict__ bet, float* __restrict__ xout,
                          __nv_bfloat16* __restrict__ xs)
{
    int row = blockIdx.x;
    const float* xr = xin + (size_t)row*DD;
    int tid = threadIdx.x;
    float v0 = xr[tid], v1 = xr[tid+256], v2 = xr[tid+512];
    float s  = v0+v1+v2;
    float ss = v0*v0 + v1*v1 + v2*v2;

    __shared__ float rs[8], rss[8], smv[2];
    int lane = tid & 31, w = tid >> 5;
#pragma unroll
    for (int off = 16; off; off >>= 1) {
        s  += __shfl_xor_sync(0xffffffffu, s,  off);
        ss += __shfl_xor_sync(0xffffffffu, ss, off);
    }
    if (lane == 0) { rs[w] = s; rss[w] = ss; }
    __syncthreads();
    if (tid == 0) {
        float S = 0.f, SSq = 0.f;
#pragma unroll
        for (int i = 0; i < 8; i++) { S += rs[i]; SSq += rss[i]; }
        float mean = S * (1.f/768.f);
        float var  = SSq * (1.f/768.f) - mean*mean;
        smv[0] = mean;
        smv[1] = rsqrtf(var + 1e-5f);
    }
    __syncthreads();
    float mean = smv[0], rstd = smv[1];
#pragma unroll
    for (int ii = 0; ii < 3; ii++) {
        int i = tid + ii*256;
        float vv = (ii==0)?v0:(ii==1)?v1:v2;
        float y = (vv - mean)*rstd*g[i] + bet[i];
        if (SPLIT == 0) {
            xout[(size_t)row*DD + i] = y;
        } else {
            __nv_bfloat16 hi = __float2bfloat16(y);
            __nv_bfloat16 lo = __float2bfloat16(y - __bfloat162float(hi));
            __nv_bfloat16* dst = xs + (size_t)row*KA1;
            dst[i]      = hi;
            dst[DD + i] = lo;
        }
    }
}

// ---------------- HMMA MLP GEMM (mma.sync bf16, stacked-K 3-term split) --------
// grid (N/128, M/128), 256 threads (8 warps: 2x4 of 64x32 warp tiles)
// MODE 0: D+bias -> gelu -> split-store into hs [row][hi: col, lo: MLPD+col]
// MODE 1: resid[row][col] += D + bias
template<int MODE>
__global__ void __launch_bounds__(256, 2)
mma_mlp_kernel(const __nv_bfloat16* __restrict__ A, const __nv_bfloat16* __restrict__ Bw,
               const float* __restrict__ bias, __nv_bfloat16* __restrict__ hs_out,
               float* __restrict__ resid, int nk, int strideA, int strideB)
{
    extern __shared__ char smc[];
    const uint32_t sbase = smem_u32(smc);
    const int tid = threadIdx.x;
    const int wid = tid >> 5, lane = tid & 31;
    const int wm = wid & 1, wn = wid >> 1;
    const int bx = blockIdx.x, by = blockIdx.y;
    const int NC = 3*nk;

    const __nv_bfloat16* Abase = A + (size_t)(by*128)*strideA;
    const __nv_bfloat16* Bbase = Bw + (size_t)(bx*128)*strideB;

    float acc[4][4][4];
#pragma unroll
    for (int i = 0; i < 4; i++)
#pragma unroll
        for (int j = 0; j < 4; j++)
#pragma unroll
            for (int q = 0; q < 4; q++) acc[i][j][q] = 0.f;

    const int lq = tid & 7;          // 16B quad in row
    const int lr = tid >> 3;         // row base

    auto load_chunk = [&](int c, int p) {
        int cwrap = (c < 2*nk) ? c : (c - 2*nk);
        const __nv_bfloat16* Ap = Abase + (size_t)cwrap*64;
        const __nv_bfloat16* Bp = Bbase + (size_t)c*64;
        uint32_t sA = sbase + p*32768;
        uint32_t sB = sA + 16384;
#pragma unroll
        for (int i = 0; i < 4; i++) {
            int r = i*32 + lr;
            uint32_t off = r*128 + lq*16;
            uint32_t sw = off ^ ((off >> 3) & 0x70);
            cp_async16(sA + sw, Ap + (size_t)r*strideA + lq*8);
            cp_async16(sB + sw, Bp + (size_t)r*strideB + lq*8);
        }
        CP_COMMIT();
    };

    const int l15 = lane & 15;
    const int lks = (lane >> 4) * 16;   // 16B k-section per ldmatrix lane

    load_chunk(0, 0);

    for (int c = 0; c < NC; c++) {
        int p = c & 1;
        if (c + 1 < NC) { load_chunk(c+1, (c+1)&1); CP_WAIT1(); }
        else            { CP_WAIT0(); }
        __syncthreads();

        uint32_t sA = sbase + p*32768;
        uint32_t sB = sA + 16384;
#pragma unroll
        for (int ks = 0; ks < 4; ks++) {
            uint32_t b0[4], b1[4];
            {
                uint32_t off = (wn*32 + l15)*128 + ks*32 + lks;
                ldmx4(b0, sB + (off ^ ((off >> 3) & 0x70)));
                off = (wn*32 + 16 + l15)*128 + ks*32 + lks;
                ldmx4(b1, sB + (off ^ ((off >> 3) & 0x70)));
            }
#pragma unroll
            for (int mt = 0; mt < 4; mt++) {
                uint32_t a[4];
                uint32_t off = (wm*64 + mt*16 + l15)*128 + ks*32 + lks;
                ldmx4(a, sA + (off ^ ((off >> 3) & 0x70)));
                mma16816(acc[mt][0], a, b0[0], b0[2]);
                mma16816(acc[mt][1], a, b0[1], b0[3]);
                mma16816(acc[mt][2], a, b1[0], b1[2]);
                mma16816(acc[mt][3], a, b1[1], b1[3]);
            }
        }
        __syncthreads();
    }

    // ---------------- epilogue (direct from registers) ----------------
    const int gm0 = by*128 + wm*64 + (lane >> 2);
    const int gn0 = bx*128 + wn*32 + (lane & 3)*2;

#pragma unroll
    for (int mt = 0; mt < 4; mt++) {
#pragma unroll
        for (int nt = 0; nt < 4; nt++) {
            int col = gn0 + nt*8;
            float bi0 = bias[col], bi1 = bias[col+1];
            int r0 = gm0 + mt*16;
            int r1 = r0 + 8;
            float v00 = acc[mt][nt][0] + bi0;
            float v01 = acc[mt][nt][1] + bi1;
            float v10 = acc[mt][nt][2] + bi0;
            float v11 = acc[mt][nt][3] + bi1;
            if (MODE == 0) {
                // exact gelu
                float g00 = 0.5f*v00*(1.f + erff(v00*0.70710678118654752f));
                float g01 = 0.5f*v01*(1.f + erff(v01*0.70710678118654752f));
                float g10 = 0.5f*v10*(1.f + erff(v10*0.70710678118654752f));
                float g11 = 0.5f*v11*(1.f + erff(v11*0.70710678118654752f));
                __nv_bfloat16 h00 = __float2bfloat16(g00);
                __nv_bfloat16 h01 = __float2bfloat16(g01);
                __nv_bfloat16 h10 = __float2bfloat16(g10);
                __nv_bfloat16 h11 = __float2bfloat16(g11);
                uint32_t hi0 = (uint32_t)*(unsigned short*)&h00 | ((uint32_t)*(unsigned short*)&h01 << 16);
                uint32_t hi1 = (uint32_t)*(unsigned short*)&h10 | ((uint32_t)*(unsigned short*)&h11 << 16);
                uint32_t lo0 = pack_bf2(g00 - __bfloat162float(h00), g01 - __bfloat162float(h01));
                uint32_t lo1 = pack_bf2(g10 - __bfloat162float(h10), g11 - __bfloat162float(h11));
                if (r0 < NTOK) {
                    *(uint32_t*)(hs_out + (size_t)r0*KA2 + col)        = hi0;
                    *(uint32_t*)(hs_out + (size_t)r0*KA2 + MLPD + col) = lo0;
                }
                if (r1 < NTOK) {
                    *(uint32_t*)(hs_out + (size_t)r1*KA2 + col)        = hi1;
                    *(uint32_t*)(hs_out + (size_t)r1*KA2 + MLPD + col) = lo1;
                }
            } else {
                if (r0 < NTOK) {
                    float2* p = (float2*)(resid + (size_t)r0*DD + col);
                    float2 t = *p; t.x += v00; t.y += v01; *p = t;
                }
                if (r1 < NTOK) {
                    float2* p = (float2*)(resid + (size_t)r1*DD + col);
                    float2 t = *p; t.x += v10; t.y += v11; *p = t;
                }
            }
        }
    }
}

// ---------------- QKV projection ----------------
__global__ void qkv_kernel(const float* __restrict__ xn,
                           const float* __restrict__ Wq, const float* __restrict__ Wk,
                           const float* __restrict__ Wv,
                           const float* __restrict__ bq, const float* __restrict__ bk,
                           const float* __restrict__ bv,
                           float* __restrict__ q, float* __restrict__ k, float* __restrict__ v)
{
    extern __shared__ float sm[];
    float* sW = sm;
    float* sb = sW + 3*64*65;
    float* sx = sb + 192;

    const int h = blockIdx.y;
    const int tok0 = blockIdx.x * 32;
    const int tid = threadIdx.x;

    for (int o = tid; o < 3*4096; o += 256) {
        int mat = o >> 12;
        int e = (o >> 6) & 63;
        int d = o & 63;
        const float* W = (mat == 0) ? Wq : (mat == 1) ? Wk : Wv;
        sW[mat*4160 + e*65 + d] = W[(size_t)(h*64 + e)*64 + d];
    }
    if (tid < 192) {
        int mat = tid / 64, e = tid % 64;
        const float* bbp = (mat == 0) ? bq : (mat == 1) ? bk : bv;
        sb[tid] = bbp[h*64 + e];
    }
    for (int o = tid; o < 2048; o += 256) {
        int t = o >> 6, d = o & 63;
        int tok = tok0 + t;
        sx[o] = (tok < NTOK) ? xn[(size_t)tok*DD + h*64 + d] : 0.f;
    }
    __syncthreads();

#pragma unroll
    for (int i = 0; i < 24; i++) {
        int o = i*256 + tid;
        int mat = o >> 11;
        int rem = o & 2047;
        int t = rem >> 6, e = rem & 63;
        int tok = tok0 + t;
        if (tok >= NTOK) continue;
        const float* wrow = &sW[mat*4160 + e*65];
        const float* xrow = &sx[t*64];
        float acc = 0.f;
#pragma unroll
        for (int d = 0; d < 64; d++) acc += xrow[d]*wrow[d];
        acc += sb[mat*64 + e];
        int b = tok / SS, s = tok % SS;
        float* dst = (mat == 0) ? q : (mat == 1) ? k : v;
        dst[(((size_t)b*NH + h)*SS + s)*DH + e] = acc;
    }
}

// ---------------- fused attention ----------------
__global__ void attn_kernel(const float* __restrict__ q, const float* __restrict__ k,
                            const float* __restrict__ v, float* __restrict__ resid)
{
    extern __shared__ float sm[];
    float* ks = sm;
    float* vs = ks + 197*65;
    float* qs = vs + 197*65;
    float* ps = qs + 256;

    const int bh = blockIdx.x;
    const int b = bh / NH, h = bh % NH;
    const size_t base = (size_t)bh * SS * DH;
    const int tid = threadIdx.x;
    const int w = tid >> 5, lane = tid & 31;

    for (int idx = tid; idx < SS*DH; idx += 128) {
        int j = idx >> 6, e = idx & 63;
        ks[j*65 + e] = k[base + idx];
        vs[j*65 + e] = v[base + idx];
    }
    __syncthreads();

    for (int s = w; s < SS; s += 4) {
        qs[w*64 + lane]      = q[base + (size_t)s*64 + lane];
        qs[w*64 + 32 + lane] = q[base + (size_t)s*64 + 32 + lane];
        __syncwarp();

        float sc[7];
        float m = -1e30f;
#pragma unroll
        for (int jj = 0; jj < 7; jj++) {
            int j = jj*32 + lane;
            float acc;
            if (j < SS) {
                const float* kr = &ks[j*65];
                const float* qr = &qs[w*64];
                acc = 0.f;
#pragma unroll
                for (int e = 0; e < 64; e++) acc += qr[e]*kr[e];
                acc *= 0.125f;
            } else acc = -1e30f;
            sc[jj] = acc;
            m = fmaxf(m, acc);
        }
#pragma unroll
        for (int off = 16; off; off >>= 1)
            m = fmaxf(m, __shfl_xor_sync(0xffffffffu, m, off));

        float sum = 0.f;
#pragma unroll
        for (int jj = 0; jj < 7; jj++) {
            int j = jj*32 + lane;
            float p = (j < SS) ? __expf(sc[jj] - m) : 0.f;
            sum += p;
            if (j < SS) ps[w*200 + j] = p;
        }
#pragma unroll
        for (int off = 16; off; off >>= 1)
            sum += __shfl_xor_sync(0xffffffffu, sum, off);
        float inv = 1.f / sum;
        __syncwarp();

        float a0 = 0.f, a1 = 0.f;
        for (int j = 0; j < SS; j++) {
            float p = ps[w*200 + j];
            a0 += p * vs[j*65 + lane];
            a1 += p * vs[j*65 + lane + 32];
        }
        size_t ridx = ((size_t)(b*SS + s))*DD + h*DH;
        resid[ridx + lane]      += a0 * inv;
        resid[ridx + 32 + lane] += a1 * inv;
        __syncwarp();
    }
}

// ---------------- classifier head ----------------
__global__ void head_kernel(const float* __restrict__ resid, const float* __restrict__ Wc,
                            const float* __restrict__ bc, float* __restrict__ out)
{
    __shared__ float sx[768];
    __shared__ float logit[1000];
    __shared__ float red[8];
    __shared__ float bscalar;

    int b = blockIdx.x;
    int tid = threadIdx.x;
    int lane = tid & 31, w = tid >> 5;

    for (int i = tid; i < 768; i += 256) sx[i] = resid[(size_t)b*SS*DD + i];
    __syncthreads();

    for (int o = tid; o < OUTC; o += 256) {
        float acc = bc[o];
        for (int kk = 0; kk < 768; kk++) acc += sx[kk]*Wc[(size_t)kk*OUTC + o];
        logit[o] = acc;
    }
    __syncthreads();

    float m = -1e30f;
    for (int o = tid; o < OUTC; o += 256) m = fmaxf(m, logit[o]);
#pragma unroll
    for (int off = 16; off; off >>= 1) m = fmaxf(m, __shfl_xor_sync(0xffffffffu, m, off));
    if (lane == 0) red[w] = m;
    __syncthreads();
    if (tid == 0) {
        float mm = red[0];
#pragma unroll
        for (int i = 1; i < 8; i++) mm = fmaxf(mm, red[i]);
        bscalar = mm;
    }
    __syncthreads();
    m = bscalar;

    float s = 0.f;
    for (int o = tid; o < OUTC; o += 256) {
        float e = __expf(logit[o] - m);
        logit[o] = e;
        s += e;
    }
#pragma unroll
    for (int off = 16; off; off >>= 1) s += __shfl_xor_sync(0xffffffffu, s, off);
    if (lane == 0) red[w] = s;
    __syncthreads();
    if (tid == 0) {
        float ssum = 0.f;
#pragma unroll
        for (int i = 0; i < 8; i++) ssum += red[i];
        bscalar = 1.f / ssum;
    }
    __syncthreads();
    float invs = bscalar;
    for (int o = tid; o < OUTC; o += 256)
        out[(size_t)b*OUTC + o] = logit[o] * invs;
}

// ---------------- launcher ----------------
extern "C" void kernel_launch(void* const* d_in, const int* in_sizes, int n_in,
                              void* d_out, int out_size)
{
    const float* x       = (const float*)d_in[0];
    const float* cls_emb = (const float*)d_in[1];
    const float* pos     = (const float*)d_in[2];
    const float* Wmap    = (const float*)d_in[3];
    const float* bmap    = (const float*)d_in[4];
    const float* ln1_g   = (const float*)d_in[5];
    const float* ln1_b   = (const float*)d_in[6];
    const float* Wq      = (const float*)d_in[7];
    const float* bq      = (const float*)d_in[8];
    const float* Wk      = (const float*)d_in[9];
    const float* bk      = (const float*)d_in[10];
    const float* Wv      = (const float*)d_in[11];
    const float* bv      = (const float*)d_in[12];
    const float* ln2_g   = (const float*)d_in[13];
    const float* ln2_b   = (const float*)d_in[14];
    const float* W1      = (const float*)d_in[15];
    const float* b1      = (const float*)d_in[16];
    const float* W2      = (const float*)d_in[17];
    const float* b2      = (const float*)d_in[18];
    const float* Wc      = (const float*)d_in[19];
    const float* bc      = (const float*)d_in[20];
    float* out = (float*)d_out;

    float *resid, *xn, *patch, *q, *k, *v;
    __nv_bfloat16 *xs, *hs, *w1p, *w2p;
    cudaGetSymbolAddress((void**)&resid, g_resid);
    cudaGetSymbolAddress((void**)&xn,    g_xn);
    cudaGetSymbolAddress((void**)&patch, g_patch);
    cudaGetSymbolAddress((void**)&q,     g_q);
    cudaGetSymbolAddress((void**)&k,     g_k);
    cudaGetSymbolAddress((void**)&v,     g_v);
    cudaGetSymbolAddress((void**)&xs,    g_xs);
    cudaGetSymbolAddress((void**)&hs,    g_hs);
    cudaGetSymbolAddress((void**)&w1p,   g_w1p);
    cudaGetSymbolAddress((void**)&w2p,   g_w2p);

    const int QKV_SMEM = (3*64*65 + 192 + 2048) * 4;
    const int ATT_SMEM = (2*197*65 + 256 + 800) * 4;
    const int MMA_SMEM = 65536;
    cudaFuncSetAttribute(qkv_kernel,  cudaFuncAttributeMaxDynamicSharedMemorySize, QKV_SMEM);
    cudaFuncSetAttribute(attn_kernel, cudaFuncAttributeMaxDynamicSharedMemorySize, ATT_SMEM);
    cudaFuncSetAttribute(mma_mlp_kernel<0>, cudaFuncAttributeMaxDynamicSharedMemorySize, MMA_SMEM);
    cudaFuncSetAttribute(mma_mlp_kernel<1>, cudaFuncAttributeMaxDynamicSharedMemorySize, MMA_SMEM);

    // weight prep (transpose + bf16 split, all layers)
    wprep_kernel<<<dim3(MLPD/32, DD/32, LL), dim3(32,32)>>>(W1, w1p, DD, MLPD);
    wprep_kernel<<<dim3(DD/32, MLPD/32, LL), dim3(32,32)>>>(W2, w2p, MLPD, DD);

    // patch embed + positional
    patchify_kernel<<<NPATCH, 256>>>(x, patch);
    sgemm_kernel<3><<<dim3(DD/128, NPATCH/128), 256>>>(patch, Wmap, bmap, resid,
                                                       NPATCH, DD, IN_DIM, pos);
    cls_init_kernel<<<BB, 256>>>(cls_emb, pos, resid);

    for (int l = 0; l < LL; l++) {
        ln_kernel<0><<<NTOK, 256>>>(resid, ln1_g + (size_t)l*DD, ln1_b + (size_t)l*DD, xn, nullptr);
        qkv_kernel<<<dim3(NTOK/32, NH), 256, QKV_SMEM>>>(
            xn,
            Wq + (size_t)l*NH*DH*DH, Wk + (size_t)l*NH*DH*DH, Wv + (size_t)l*NH*DH*DH,
            bq + (size_t)l*NH*DH,    bk + (size_t)l*NH*DH,    bv + (size_t)l*NH*DH,
            q, k, v);
        attn_kernel<<<BB*NH, 128, ATT_SMEM>>>(q, k, v, resid);

        ln_kernel<1><<<NTOK, 256>>>(resid, ln2_g + (size_t)l*DD, ln2_b + (size_t)l*DD, nullptr, xs);
        mma_mlp_kernel<0><<<dim3(MLPD/128, MPAD/128), 256, MMA_SMEM>>>(
            xs, w1p + (size_t)l*MLPD*KB1, b1 + (size_t)l*MLPD, hs, nullptr, 12, KA1, KB1);
        mma_mlp_kernel<1><<<dim3(DD/128, MPAD/128), 256, MMA_SMEM>>>(
            hs, w2p + (size_t)l*DD*KB2, b2 + (size_t)l*DD, nullptr, resid, 48, KA2, KB2);
    }

    head_kernel<<<BB, 256>>>(resid, Wc, bc, out);
}

// round 4
// speedup vs baseline: 2.4117x; 1.4520x over previous
#include <cuda_runtime.h>
#include <cuda_bf16.h>
#include <math.h>
#include <stdint.h>

// ---------------- problem constants ----------------
#define BB      32
#define CC      3
#define IMG     224
#define NP      14
#define PS      16
#define IN_DIM  768
#define DD      768
#define NH      12
#define DH      64
#define LL      12
#define MLPD    3072
#define OUTC    1000
#define SS      197          // NP*NP + 1
#define NTOK    (BB*SS)      // 6304
#define NPATCH  (BB*NP*NP)   // 6272
#define MPAD    6400         // NTOK padded to 50*128

#define KA1     (2*DD)       // 1536: A storage [hi|lo] for GEMM1 / QKV
#define KB1     (3*DD)       // 2304: B storage [hi|hi|lo]
#define KA2     (2*MLPD)     // 6144
#define KB2     (3*MLPD)     // 9216

// ---------------- scratch (device globals; no runtime alloc) ----------------
static __device__ float g_resid[NTOK*DD];
static __device__ float g_patch[NPATCH*IN_DIM];
static __device__ float g_q[NTOK*DD];
static __device__ float g_k[NTOK*DD];
static __device__ float g_v[NTOK*DD];
static __device__ __nv_bfloat16 g_xs[(size_t)MPAD*KA2];     // split activations (ln out / gelu out)
static __device__ __nv_bfloat16 g_hs[(size_t)MPAD*KA2];     // split gelu activations
static __device__ __nv_bfloat16 g_w1p[(size_t)LL*MLPD*KB1]; // W1 transposed+split
static __device__ __nv_bfloat16 g_w2p[(size_t)LL*DD*KB2];   // W2 transposed+split
static __device__ __nv_bfloat16 g_wqkv[(size_t)LL*3*NH*64*192]; // QKV weights split

// ================= arch-generic tensor-core helpers =================
__device__ __forceinline__ uint32_t smem_u32(const void* p) {
    uint32_t a;
    asm("{ .reg .u64 t; cvta.to.shared.u64 t, %1; cvt.u32.u64 %0, t; }" : "=r"(a) : "l"(p));
    return a;
}
__device__ __forceinline__ void cp_async16(uint32_t smem, const void* g) {
    asm volatile("cp.async.cg.shared.global [%0], [%1], 16;" :: "r"(smem), "l"(g));
}
#define CP_COMMIT() asm volatile("cp.async.commit_group;" ::: "memory")
#define CP_WAIT1()  asm volatile("cp.async.wait_group 1;" ::: "memory")
#define CP_WAIT0()  asm volatile("cp.async.wait_group 0;" ::: "memory")

__device__ __forceinline__ void ldmx4(uint32_t* r, uint32_t addr) {
    asm volatile("ldmatrix.sync.aligned.m8n8.x4.shared.b16 {%0,%1,%2,%3}, [%4];"
        : "=r"(r[0]), "=r"(r[1]), "=r"(r[2]), "=r"(r[3]) : "r"(addr));
}
__device__ __forceinline__ void mma16816(float* d, const uint32_t* a, uint32_t b0, uint32_t b1) {
    asm volatile(
        "mma.sync.aligned.m16n8k16.row.col.f32.bf16.bf16.f32 "
        "{%0,%1,%2,%3}, {%4,%5,%6,%7}, {%8,%9}, {%0,%1,%2,%3};"
        : "+f"(d[0]), "+f"(d[1]), "+f"(d[2]), "+f"(d[3])
        : "r"(a[0]), "r"(a[1]), "r"(a[2]), "r"(a[3]), "r"(b0), "r"(b1));
}
__device__ __forceinline__ uint32_t pack_bf2(float x, float y) {
    __nv_bfloat162 t = __floats2bfloat162_rn(x, y);
    return *(uint32_t*)&t;
}

// ---------------- patchify ----------------
__global__ void patchify_kernel(const float* __restrict__ x, float* __restrict__ patch)
{
    int m = blockIdx.x;
    int b = m / (NP*NP);
    int p = m % (NP*NP);
    int py = p / NP, px = p % NP;
    for (int i = threadIdx.x; i < IN_DIM; i += blockDim.x) {
        int c = i >> 8;
        int r = (i >> 4) & 15;
        int s = i & 15;
        size_t src = ((size_t)(b*CC + c)*IMG + (py*PS + r))*IMG + (px*PS + s);
        patch[(size_t)m*IN_DIM + i] = x[src];
    }
}

__global__ void cls_init_kernel(const float* __restrict__ cls_emb,
                                const float* __restrict__ pos,
                                float* __restrict__ resid)
{
    int b = blockIdx.x;
    for (int d = threadIdx.x; d < DD; d += blockDim.x)
        resid[(size_t)b*SS*DD + d] = cls_emb[d] + pos[d];
}

// ---------------- fp32 SGEMM (patch embed only) ----------------
__global__ void sgemm_embed_kernel(const float* __restrict__ A, const float* __restrict__ Bm,
                                   const float* __restrict__ bias, float* __restrict__ C,
                                   int M, int N, int K, const float* __restrict__ extra)
{
    __shared__ float As[8*128];
    __shared__ float Bs[8*128];

    const int tid = threadIdx.x;
    const int bx = blockIdx.x, by = blockIdx.y;
    const int tx = tid & 15, ty = tid >> 4;

    float acc[8][8];
#pragma unroll
    for (int i = 0; i < 8; i++)
#pragma unroll
        for (int j = 0; j < 8; j++) acc[i][j] = 0.f;

    const int aRow = tid >> 1;
    const int aK   = (tid & 1) * 4;
    const int bK   = tid >> 5;
    const int bCol = (tid & 31) * 4;
    const int globARow = by*128 + aRow;

    for (int k0 = 0; k0 < K; k0 += 8) {
        float4 av;
        if (globARow < M) av = *(const float4*)(A + (size_t)globARow*K + k0 + aK);
        else              av = make_float4(0.f,0.f,0.f,0.f);
        As[(aK+0)*128 + aRow] = av.x;
        As[(aK+1)*128 + aRow] = av.y;
        As[(aK+2)*128 + aRow] = av.z;
        As[(aK+3)*128 + aRow] = av.w;
        float4 bv = *(const float4*)(Bm + (size_t)(k0 + bK)*N + bx*128 + bCol);
        *(float4*)(Bs + bK*128 + bCol) = bv;
        __syncthreads();

#pragma unroll
        for (int kk = 0; kk < 8; kk++) {
            float a[8], b[8];
#pragma unroll
            for (int i = 0; i < 4; i++) {
                a[i]   = As[kk*128 + ty*4 + i];
                a[4+i] = As[kk*128 + 64 + ty*4 + i];
                b[i]   = Bs[kk*128 + tx*4 + i];
                b[4+i] = Bs[kk*128 + 64 + tx*4 + i];
            }
#pragma unroll
            for (int i = 0; i < 8; i++)
#pragma unroll
                for (int j = 0; j < 8; j++)
                    acc[i][j] += a[i]*b[j];
        }
        __syncthreads();
    }

#pragma unroll
    for (int i = 0; i < 8; i++) {
        int r = (i < 4) ? (ty*4 + i) : (64 + ty*4 + (i-4));
        int row = by*128 + r;
        if (row >= M) continue;
#pragma unroll
        for (int j = 0; j < 8; j++) {
            int cc = (j < 4) ? (tx*4 + j) : (64 + tx*4 + (j-4));
            int col = bx*128 + cc;
            float val = acc[i][j] + bias[col];
            int bb = row / (NP*NP);
            int pp = row % (NP*NP);
            int orow = bb*SS + 1 + pp;
            C[(size_t)orow*DD + col] = val + extra[(size_t)(pp+1)*DD + col];
        }
    }
}

// ---------------- weight prep: transpose + bf16 split, stacked K ----------------
__global__ void wprep_kernel(const float* __restrict__ W, __nv_bfloat16* __restrict__ Wp,
                             int K, int N)
{
    __shared__ float t[32][33];
    int l = blockIdx.z;
    const float* Wl = W + (size_t)l*K*N;
    __nv_bfloat16* Wpl = Wp + (size_t)l*N*3*K;
    int n0 = blockIdx.x*32, k0 = blockIdx.y*32;
    int tx = threadIdx.x, ty = threadIdx.y;

    t[ty][tx] = Wl[(size_t)(k0+ty)*N + n0+tx];
    __syncthreads();
    float v = t[tx][ty];
    int row = n0+ty, col = k0+tx;
    __nv_bfloat16 hi = __float2bfloat16(v);
    __nv_bfloat16 lo = __float2bfloat16(v - __bfloat162float(hi));
    __nv_bfloat16* dst = Wpl + (size_t)row*3*K;
    dst[col]       = hi;
    dst[K + col]   = hi;
    dst[2*K + col] = lo;
}

// ---------------- QKV weight prep: per (l, mat, h): 64x64 -> [e][wh|wh|wl] ----
__global__ void qkv_prep_kernel(const float* __restrict__ Wq, const float* __restrict__ Wk,
                                const float* __restrict__ Wv, __nv_bfloat16* __restrict__ wout)
{
    int h = blockIdx.x, mat = blockIdx.y, l = blockIdx.z;
    const float* W = (mat == 0) ? Wq : (mat == 1) ? Wk : Wv;
    const float* Wl = W + (size_t)(l*NH + h)*64*64;
    __nv_bfloat16* dst = wout + (size_t)((l*3 + mat)*NH + h)*64*192;
    for (int idx = threadIdx.x; idx < 4096; idx += 256) {
        int e = idx >> 6, d = idx & 63;
        float v = Wl[e*64 + d];
        __nv_bfloat16 hi = __float2bfloat16(v);
        __nv_bfloat16 lo = __float2bfloat16(v - __bfloat162float(hi));
        dst[e*192 + d]       = hi;
        dst[e*192 + 64 + d]  = hi;
        dst[e*192 + 128 + d] = lo;
    }
}

// ---------------- LayerNorm -> split bf16 [row][hi(768)|lo(768)] ----------------
__global__ void ln_kernel(const float* __restrict__ xin, const float* __restrict__ g,
                          const float* __restrict__ bet, __nv_bfloat16* __restrict__ xs)
{
    int row = blockIdx.x;
    const float* xr = xin + (size_t)row*DD;
    int tid = threadIdx.x;
    float v0 = xr[tid], v1 = xr[tid+256], v2 = xr[tid+512];
    float s  = v0+v1+v2;
    float ss = v0*v0 + v1*v1 + v2*v2;

    __shared__ float rs[8], rss[8], smv[2];
    int lane = tid & 31, w = tid >> 5;
#pragma unroll
    for (int off = 16; off; off >>= 1) {
        s  += __shfl_xor_sync(0xffffffffu, s,  off);
        ss += __shfl_xor_sync(0xffffffffu, ss, off);
    }
    if (lane == 0) { rs[w] = s; rss[w] = ss; }
    __syncthreads();
    if (tid == 0) {
        float S = 0.f, SSq = 0.f;
#pragma unroll
        for (int i = 0; i < 8; i++) { S += rs[i]; SSq += rss[i]; }
        float mean = S * (1.f/768.f);
        float var  = SSq * (1.f/768.f) - mean*mean;
        smv[0] = mean;
        smv[1] = rsqrtf(var + 1e-5f);
    }
    __syncthreads();
    float mean = smv[0], rstd = smv[1];
#pragma unroll
    for (int ii = 0; ii < 3; ii++) {
        int i = tid + ii*256;
        float vv = (ii==0)?v0:(ii==1)?v1:v2;
        float y = (vv - mean)*rstd*g[i] + bet[i];
        __nv_bfloat16 hi = __float2bfloat16(y);
        __nv_bfloat16 lo = __float2bfloat16(y - __bfloat162float(hi));
        __nv_bfloat16* dst = xs + (size_t)row*KA1;
        dst[i]      = hi;
        dst[DD + i] = lo;
    }
}

// ---------------- HMMA MLP GEMM (mma.sync bf16, stacked-K 3-term split) --------
template<int MODE>
__global__ void __launch_bounds__(256, 2)
mma_mlp_kernel(const __nv_bfloat16* __restrict__ A, const __nv_bfloat16* __restrict__ Bw,
               const float* __restrict__ bias, __nv_bfloat16* __restrict__ hs_out,
               float* __restrict__ resid, int nk, int strideA, int strideB)
{
    extern __shared__ char smc[];
    const uint32_t sbase = smem_u32(smc);
    const int tid = threadIdx.x;
    const int wid = tid >> 5, lane = tid & 31;
    const int wm = wid & 1, wn = wid >> 1;
    const int bx = blockIdx.x, by = blockIdx.y;
    const int NC = 3*nk;

    const __nv_bfloat16* Abase = A + (size_t)(by*128)*strideA;
    const __nv_bfloat16* Bbase = Bw + (size_t)(bx*128)*strideB;

    float acc[4][4][4];
#pragma unroll
    for (int i = 0; i < 4; i++)
#pragma unroll
        for (int j = 0; j < 4; j++)
#pragma unroll
            for (int q = 0; q < 4; q++) acc[i][j][q] = 0.f;

    const int lq = tid & 7;
    const int lr = tid >> 3;

    auto load_chunk = [&](int c, int p) {
        int cwrap = (c < 2*nk) ? c : (c - 2*nk);
        const __nv_bfloat16* Ap = Abase + (size_t)cwrap*64;
        const __nv_bfloat16* Bp = Bbase + (size_t)c*64;
        uint32_t sA = sbase + p*32768;
        uint32_t sB = sA + 16384;
#pragma unroll
        for (int i = 0; i < 4; i++) {
            int r = i*32 + lr;
            uint32_t off = r*128 + lq*16;
            uint32_t sw = off ^ ((off >> 3) & 0x70);
            cp_async16(sA + sw, Ap + (size_t)r*strideA + lq*8);
            cp_async16(sB + sw, Bp + (size_t)r*strideB + lq*8);
        }
        CP_COMMIT();
    };

    const int l15 = lane & 15;
    const int lks = (lane >> 4) * 16;

    load_chunk(0, 0);

    for (int c = 0; c < NC; c++) {
        int p = c & 1;
        if (c + 1 < NC) { load_chunk(c+1, (c+1)&1); CP_WAIT1(); }
        else            { CP_WAIT0(); }
        __syncthreads();

        uint32_t sA = sbase + p*32768;
        uint32_t sB = sA + 16384;
#pragma unroll
        for (int ks = 0; ks < 4; ks++) {
            uint32_t b0[4], b1[4];
            {
                uint32_t off = (wn*32 + l15)*128 + ks*32 + lks;
                ldmx4(b0, sB + (off ^ ((off >> 3) & 0x70)));
                off = (wn*32 + 16 + l15)*128 + ks*32 + lks;
                ldmx4(b1, sB + (off ^ ((off >> 3) & 0x70)));
            }
#pragma unroll
            for (int mt = 0; mt < 4; mt++) {
                uint32_t a[4];
                uint32_t off = (wm*64 + mt*16 + l15)*128 + ks*32 + lks;
                ldmx4(a, sA + (off ^ ((off >> 3) & 0x70)));
                mma16816(acc[mt][0], a, b0[0], b0[2]);
                mma16816(acc[mt][1], a, b0[1], b0[3]);
                mma16816(acc[mt][2], a, b1[0], b1[2]);
                mma16816(acc[mt][3], a, b1[1], b1[3]);
            }
        }
        __syncthreads();
    }

    const int gm0 = by*128 + wm*64 + (lane >> 2);
    const int gn0 = bx*128 + wn*32 + (lane & 3)*2;

#pragma unroll
    for (int mt = 0; mt < 4; mt++) {
#pragma unroll
        for (int nt = 0; nt < 4; nt++) {
            int col = gn0 + nt*8;
            float bi0 = bias[col], bi1 = bias[col+1];
            int r0 = gm0 + mt*16;
            int r1 = r0 + 8;
            float v00 = acc[mt][nt][0] + bi0;
            float v01 = acc[mt][nt][1] + bi1;
            float v10 = acc[mt][nt][2] + bi0;
            float v11 = acc[mt][nt][3] + bi1;
            if (MODE == 0) {
                float g00 = 0.5f*v00*(1.f + erff(v00*0.70710678118654752f));
                float g01 = 0.5f*v01*(1.f + erff(v01*0.70710678118654752f));
                float g10 = 0.5f*v10*(1.f + erff(v10*0.70710678118654752f));
                float g11 = 0.5f*v11*(1.f + erff(v11*0.70710678118654752f));
                __nv_bfloat16 h00 = __float2bfloat16(g00);
                __nv_bfloat16 h01 = __float2bfloat16(g01);
                __nv_bfloat16 h10 = __float2bfloat16(g10);
                __nv_bfloat16 h11 = __float2bfloat16(g11);
                uint32_t hi0 = (uint32_t)*(unsigned short*)&h00 | ((uint32_t)*(unsigned short*)&h01 << 16);
                uint32_t hi1 = (uint32_t)*(unsigned short*)&h10 | ((uint32_t)*(unsigned short*)&h11 << 16);
                uint32_t lo0 = pack_bf2(g00 - __bfloat162float(h00), g01 - __bfloat162float(h01));
                uint32_t lo1 = pack_bf2(g10 - __bfloat162float(h10), g11 - __bfloat162float(h11));
                if (r0 < NTOK) {
                    *(uint32_t*)(hs_out + (size_t)r0*KA2 + col)        = hi0;
                    *(uint32_t*)(hs_out + (size_t)r0*KA2 + MLPD + col) = lo0;
                }
                if (r1 < NTOK) {
                    *(uint32_t*)(hs_out + (size_t)r1*KA2 + col)        = hi1;
                    *(uint32_t*)(hs_out + (size_t)r1*KA2 + MLPD + col) = lo1;
                }
            } else {
                if (r0 < NTOK) {
                    float2* p = (float2*)(resid + (size_t)r0*DD + col);
                    float2 t = *p; t.x += v00; t.y += v01; *p = t;
                }
                if (r1 < NTOK) {
                    float2* p = (float2*)(resid + (size_t)r1*DD + col);
                    float2 t = *p; t.x += v10; t.y += v11; *p = t;
                }
            }
        }
    }
}

// ---------------- HMMA QKV projection -----------------------------------------
// grid (3*NH, MPAD/128), 128 threads (4 warps, each 32 rows x 64 cols)
// A = xs split [row][hi|lo]; chunks {hi@h64, lo@768+h64, hi@h64}
// B = wqkv [(l*3+mat)*NH+h][e][192] = [wh|wh|wl]
__global__ void __launch_bounds__(128, 2)
qkv_mma_kernel(const __nv_bfloat16* __restrict__ xs, const __nv_bfloat16* __restrict__ wqkv,
               const float* __restrict__ bq, const float* __restrict__ bk,
               const float* __restrict__ bv,
               float* __restrict__ q, float* __restrict__ k, float* __restrict__ v)
{
    extern __shared__ char smc[];
    const uint32_t sbase = smem_u32(smc);
    const int tid = threadIdx.x;
    const int wid = tid >> 5, lane = tid & 31;
    const int hm = blockIdx.x;
    const int mat = hm / NH, h = hm % NH;
    const int by = blockIdx.y;

    const __nv_bfloat16* Wp = wqkv + (size_t)hm*64*192;
    const float* bias = (mat == 0) ? bq : (mat == 1) ? bk : bv;
    float* dst = (mat == 0) ? q : (mat == 1) ? k : v;

    // loads: A 3 chunks of 128x64 (16KB each), B 3 chunks of 64x64 (8KB each)
    const int lq = tid & 7, lr = tid >> 3;   // lr 0..15
    const int colOff[3] = { h*64, DD + h*64, h*64 };
#pragma unroll
    for (int c = 0; c < 3; c++) {
        const __nv_bfloat16* Ap = xs + colOff[c];
#pragma unroll
        for (int i = 0; i < 8; i++) {
            int r = i*16 + lr;
            uint32_t off = r*128 + lq*16;
            uint32_t sw = off ^ ((off >> 3) & 0x70);
            cp_async16(sbase + c*16384 + sw, Ap + (size_t)(by*128 + r)*KA1 + lq*8);
        }
#pragma unroll
        for (int i = 0; i < 4; i++) {
            int r = i*16 + lr;
            if (r < 64) {
                uint32_t off = r*128 + lq*16;
                uint32_t sw = off ^ ((off >> 3) & 0x70);
                cp_async16(sbase + 49152 + c*8192 + sw, Wp + (size_t)r*192 + c*64 + lq*8);
            }
        }
    }
    CP_COMMIT();
    CP_WAIT0();
    __syncthreads();

    float acc[2][8][4];
#pragma unroll
    for (int i = 0; i < 2; i++)
#pragma unroll
        for (int j = 0; j < 8; j++)
#pragma unroll
            for (int t = 0; t < 4; t++) acc[i][j][t] = 0.f;

    const int l15 = lane & 15;
    const int lks = (lane >> 4) * 16;
    const int m0 = wid*32;

#pragma unroll
    for (int c = 0; c < 3; c++) {
        uint32_t sA = sbase + c*16384;
        uint32_t sB = sbase + 49152 + c*8192;
#pragma unroll
        for (int ks = 0; ks < 4; ks++) {
            uint32_t b[4][4];
#pragma unroll
            for (int nb = 0; nb < 4; nb++) {
                uint32_t off = (nb*16 + l15)*128 + ks*32 + lks;
                ldmx4(b[nb], sB + (off ^ ((off >> 3) & 0x70)));
            }
#pragma unroll
            for (int mt = 0; mt < 2; mt++) {
                uint32_t a[4];
                uint32_t off = (m0 + mt*16 + l15)*128 + ks*32 + lks;
                ldmx4(a, sA + (off ^ ((off >> 3) & 0x70)));
#pragma unroll
                for (int nb = 0; nb < 4; nb++) {
                    mma16816(acc[mt][2*nb],   a, b[nb][0], b[nb][2]);
                    mma16816(acc[mt][2*nb+1], a, b[nb][1], b[nb][3]);
                }
            }
        }
    }

    // epilogue: write fp32 q/k/v [(b*NH+h)*SS + s][e]
#pragma unroll
    for (int mt = 0; mt < 2; mt++) {
#pragma unroll
        for (int nt = 0; nt < 8; nt++) {
            int e = nt*8 + (lane & 3)*2;
            float bi0 = bias[h*64 + e], bi1 = bias[h*64 + e + 1];
            int r0 = by*128 + m0 + mt*16 + (lane >> 2);
            int r1 = r0 + 8;
            if (r0 < NTOK) {
                int b = r0 / SS, s = r0 % SS;
                float2* p = (float2*)(dst + (((size_t)b*NH + h)*SS + s)*DH + e);
                *p = make_float2(acc[mt][nt][0] + bi0, acc[mt][nt][1] + bi1);
            }
            if (r1 < NTOK) {
                int b = r1 / SS, s = r1 % SS;
                float2* p = (float2*)(dst + (((size_t)b*NH + h)*SS + s)*DH + e);
                *p = make_float2(acc[mt][nt][2] + bi0, acc[mt][nt][3] + bi1);
            }
        }
    }
}

// ---------------- fused attention (4-row blocked, 384 threads) ----------------
#define KVP 68
#define ATT_WARPS 12
__global__ void __launch_bounds__(384, 1)
attn_kernel(const float* __restrict__ q, const float* __restrict__ k,
            const float* __restrict__ v, float* __restrict__ resid)
{
    extern __shared__ float sm[];
    float* ks = sm;                          // 197*68
    float* vs = ks + SS*KVP;                 // 197*68
    float* qs = vs + SS*KVP;                 // 12*4*68
    float* ps = qs + ATT_WARPS*4*KVP;        // 12*4*200

    const int bh = blockIdx.x;
    const int b = bh / NH, h = bh % NH;
    const size_t base = (size_t)bh * SS * DH;
    const int tid = threadIdx.x;
    const int w = tid >> 5, lane = tid & 31;

    // load K,V (float4)
    for (int idx = tid; idx < SS*16; idx += 384) {
        int j = idx >> 4, e4 = (idx & 15) * 4;
        *(float4*)&ks[j*KVP + e4] = *(const float4*)(k + base + (size_t)j*64 + e4);
        *(float4*)&vs[j*KVP + e4] = *(const float4*)(v + base + (size_t)j*64 + e4);
    }
    __syncthreads();

    float* qw = qs + w*4*KVP;
    float* pw = ps + w*4*200;

    for (int pass = 0; pass < 5; pass++) {
        int s0 = pass*48 + w*4;

        // stage 4 q rows
        for (int t = lane; t < 4*64; t += 32) {
            int r = t >> 6, e = t & 63;
            float val = (s0 + r < SS) ? q[base + (size_t)(s0 + r)*64 + e] : 0.f;
            qw[r*KVP + e] = val;
        }
        __syncwarp();

        // scores: sc[jj][r]
        float sc[7][4];
#pragma unroll
        for (int jj = 0; jj < 7; jj++)
#pragma unroll
            for (int r = 0; r < 4; r++) sc[jj][r] = 0.f;

#pragma unroll 4
        for (int e16 = 0; e16 < 16; e16++) {
            float4 q4[4];
#pragma unroll
            for (int r = 0; r < 4; r++) q4[r] = *(float4*)&qw[r*KVP + e16*4];
#pragma unroll
            for (int jj = 0; jj < 7; jj++) {
                int j = jj*32 + lane;
                float4 kv = (j < SS) ? *(float4*)&ks[j*KVP + e16*4]
                                     : make_float4(0.f,0.f,0.f,0.f);
#pragma unroll
                for (int r = 0; r < 4; r++) {
                    sc[jj][r] += q4[r].x*kv.x + q4[r].y*kv.y + q4[r].z*kv.z + q4[r].w*kv.w;
                }
            }
        }

        // softmax per row
        float inv[4];
#pragma unroll
        for (int r = 0; r < 4; r++) {
            float m = -1e30f;
#pragma unroll
            for (int jj = 0; jj < 7; jj++) {
                int j = jj*32 + lane;
                float val = (j < SS) ? sc[jj][r]*0.125f : -1e30f;
                sc[jj][r] = val;
                m = fmaxf(m, val);
            }
#pragma unroll
            for (int off = 16; off; off >>= 1)
                m = fmaxf(m, __shfl_xor_sync(0xffffffffu, m, off));
            float sum = 0.f;
#pragma unroll
            for (int jj = 0; jj < 7; jj++) {
                int j = jj*32 + lane;
                float p = (j < SS) ? __expf(sc[jj][r] - m) : 0.f;
                sum += p;
                if (j < SS) pw[r*200 + j] = p;
            }
#pragma unroll
            for (int off = 16; off; off >>= 1)
                sum += __shfl_xor_sync(0xffffffffu, sum, off);
            inv[r] = 1.f / sum;
        }
        __syncwarp();

        // PV
        float o0[4] = {0.f,0.f,0.f,0.f}, o1[4] = {0.f,0.f,0.f,0.f};
#pragma unroll 4
        for (int j = 0; j < SS; j++) {
            float v0 = vs[j*KVP + lane];
            float v1 = vs[j*KVP + 32 + lane];
#pragma unroll
            for (int r = 0; r < 4; r++) {
                float p = pw[r*200 + j];
                o0[r] += p*v0;
                o1[r] += p*v1;
            }
        }

#pragma unroll
        for (int r = 0; r < 4; r++) {
            int s = s0 + r;
            if (s < SS) {
                size_t ridx = ((size_t)(b*SS + s))*DD + h*DH;
                resid[ridx + lane]      += o0[r]*inv[r];
                resid[ridx + 32 + lane] += o1[r]*inv[r];
            }
        }
        __syncwarp();
    }
}

// ---------------- classifier head ----------------
__global__ void head_kernel(const float* __restrict__ resid, const float* __restrict__ Wc,
                            const float* __restrict__ bc, float* __restrict__ out)
{
    __shared__ float sx[768];
    __shared__ float logit[1000];
    __shared__ float red[8];
    __shared__ float bscalar;

    int b = blockIdx.x;
    int tid = threadIdx.x;
    int lane = tid & 31, w = tid >> 5;

    for (int i = tid; i < 768; i += 256) sx[i] = resid[(size_t)b*SS*DD + i];
    __syncthreads();

    for (int o = tid; o < OUTC; o += 256) {
        float acc = bc[o];
        for (int kk = 0; kk < 768; kk++) acc += sx[kk]*Wc[(size_t)kk*OUTC + o];
        logit[o] = acc;
    }
    __syncthreads();

    float m = -1e30f;
    for (int o = tid; o < OUTC; o += 256) m = fmaxf(m, logit[o]);
#pragma unroll
    for (int off = 16; off; off >>= 1) m = fmaxf(m, __shfl_xor_sync(0xffffffffu, m, off));
    if (lane == 0) red[w] = m;
    __syncthreads();
    if (tid == 0) {
        float mm = red[0];
#pragma unroll
        for (int i = 1; i < 8; i++) mm = fmaxf(mm, red[i]);
        bscalar = mm;
    }
    __syncthreads();
    m = bscalar;

    float s = 0.f;
    for (int o = tid; o < OUTC; o += 256) {
        float e = __expf(logit[o] - m);
        logit[o] = e;
        s += e;
    }
#pragma unroll
    for (int off = 16; off; off >>= 1) s += __shfl_xor_sync(0xffffffffu, s, off);
    if (lane == 0) red[w] = s;
    __syncthreads();
    if (tid == 0) {
        float ssum = 0.f;
#pragma unroll
        for (int i = 0; i < 8; i++) ssum += red[i];
        bscalar = 1.f / ssum;
    }
    __syncthreads();
    float invs = bscalar;
    for (int o = tid; o < OUTC; o += 256)
        out[(size_t)b*OUTC + o] = logit[o] * invs;
}

// ---------------- launcher ----------------
extern "C" void kernel_launch(void* const* d_in, const int* in_sizes, int n_in,
                              void* d_out, int out_size)
{
    const float* x       = (const float*)d_in[0];
    const float* cls_emb = (const float*)d_in[1];
    const float* pos     = (const float*)d_in[2];
    const float* Wmap    = (const float*)d_in[3];
    const float* bmap    = (const float*)d_in[4];
    const float* ln1_g   = (const float*)d_in[5];
    const float* ln1_b   = (const float*)d_in[6];
    const float* Wq      = (const float*)d_in[7];
    const float* bq      = (const float*)d_in[8];
    const float* Wk      = (const float*)d_in[9];
    const float* bk      = (const float*)d_in[10];
    const float* Wv      = (const float*)d_in[11];
    const float* bv      = (const float*)d_in[12];
    const float* ln2_g   = (const float*)d_in[13];
    const float* ln2_b   = (const float*)d_in[14];
    const float* W1      = (const float*)d_in[15];
    const float* b1      = (const float*)d_in[16];
    const float* W2      = (const float*)d_in[17];
    const float* b2      = (const float*)d_in[18];
    const float* Wc      = (const float*)d_in[19];
    const float* bc      = (const float*)d_in[20];
    float* out = (float*)d_out;

    float *resid, *patch, *q, *k, *v;
    __nv_bfloat16 *xs, *hs, *w1p, *w2p, *wqkv;
    cudaGetSymbolAddress((void**)&resid, g_resid);
    cudaGetSymbolAddress((void**)&patch, g_patch);
    cudaGetSymbolAddress((void**)&q,     g_q);
    cudaGetSymbolAddress((void**)&k,     g_k);
    cudaGetSymbolAddress((void**)&v,     g_v);
    cudaGetSymbolAddress((void**)&xs,    g_xs);
    cudaGetSymbolAddress((void**)&hs,    g_hs);
    cudaGetSymbolAddress((void**)&w1p,   g_w1p);
    cudaGetSymbolAddress((void**)&w2p,   g_w2p);
    cudaGetSymbolAddress((void**)&wqkv,  g_wqkv);

    const int ATT_SMEM = (2*SS*KVP + ATT_WARPS*4*KVP + ATT_WARPS*4*200) * 4;
    const int MMA_SMEM = 65536;
    const int QKV_SMEM = 3*16384 + 3*8192;   // 73,728 B
    cudaFuncSetAttribute(attn_kernel, cudaFuncAttributeMaxDynamicSharedMemorySize, ATT_SMEM);
    cudaFuncSetAttribute(mma_mlp_kernel<0>, cudaFuncAttributeMaxDynamicSharedMemorySize, MMA_SMEM);
    cudaFuncSetAttribute(mma_mlp_kernel<1>, cudaFuncAttributeMaxDynamicSharedMemorySize, MMA_SMEM);
    cudaFuncSetAttribute(qkv_mma_kernel, cudaFuncAttributeMaxDynamicSharedMemorySize, QKV_SMEM);

    // weight prep
    wprep_kernel<<<dim3(MLPD/32, DD/32, LL), dim3(32,32)>>>(W1, w1p, DD, MLPD);
    wprep_kernel<<<dim3(DD/32, MLPD/32, LL), dim3(32,32)>>>(W2, w2p, MLPD, DD);
    qkv_prep_kernel<<<dim3(NH, 3, LL), 256>>>(Wq, Wk, Wv, wqkv);

    // patch embed + positional
    patchify_kernel<<<NPATCH, 256>>>(x, patch);
    sgemm_embed_kernel<<<dim3(DD/128, NPATCH/128), 256>>>(patch, Wmap, bmap, resid,
                                                          NPATCH, DD, IN_DIM, pos);
    cls_init_kernel<<<BB, 256>>>(cls_emb, pos, resid);

    for (int l = 0; l < LL; l++) {
        ln_kernel<<<NTOK, 256>>>(resid, ln1_g + (size_t)l*DD, ln1_b + (size_t)l*DD, xs);
        qkv_mma_kernel<<<dim3(3*NH, MPAD/128), 128, QKV_SMEM>>>(
            xs, wqkv + (size_t)l*3*NH*64*192,
            bq + (size_t)l*NH*DH, bk + (size_t)l*NH*DH, bv + (size_t)l*NH*DH,
            q, k, v);
        attn_kernel<<<BB*NH, 384, ATT_SMEM>>>(q, k, v, resid);

        ln_kernel<<<NTOK, 256>>>(resid, ln2_g + (size_t)l*DD, ln2_b + (size_t)l*DD, xs);
        mma_mlp_kernel<0><<<dim3(MLPD/128, MPAD/128), 256, MMA_SMEM>>>(
            xs, w1p + (size_t)l*MLPD*KB1, b1 + (size_t)l*MLPD, hs, nullptr, 12, KA1, KB1);
        mma_mlp_kernel<1><<<dim3(DD/128, MPAD/128), 256, MMA_SMEM>>>(
            hs, w2p + (size_t)l*DD*KB2, b2 + (size_t)l*DD, nullptr, resid, 48, KA2, KB2);
    }

    head_kernel<<<BB, 256>>>(resid, Wc, bc, out);
}

// round 5
// speedup vs baseline: 2.5699x; 1.0656x over previous
#include <cuda_runtime.h>
#include <cuda_bf16.h>
#include <math.h>
#include <stdint.h>

// ---------------- problem constants ----------------
#define BB      32
#define CC      3
#define IMG     224
#define NP      14
#define PS      16
#define IN_DIM  768
#define DD      768
#define NH      12
#define DH      64
#define LL      12
#define MLPD    3072
#define OUTC    1000
#define SS      197          // NP*NP + 1
#define NTOK    (BB*SS)      // 6304
#define NPATCH  (BB*NP*NP)   // 6272
#define MPAD    6400         // NTOK padded to 50*128

#define KA1     (2*DD)       // 1536: A storage [hi|lo]
#define KB1     (3*DD)       // 2304: B storage [hi|hi|lo]
#define KA2     (2*MLPD)     // 6144
#define KB2     (3*MLPD)     // 9216

#define SPAD    208          // padded seq len for attention tiles
#define VTP     232          // V^T row pitch (elems); 464B rows, conflict-free ldmatrix

// ---------------- scratch (device globals; no runtime alloc) ----------------
static __device__ float g_resid[NTOK*DD];
static __device__ float g_patch[NPATCH*IN_DIM];
static __device__ __nv_bfloat16 g_xs[(size_t)MPAD*KA1];
static __device__ __nv_bfloat16 g_hs[(size_t)MPAD*KA2];
static __device__ __nv_bfloat16 g_w1p[(size_t)LL*MLPD*KB1];
static __device__ __nv_bfloat16 g_w2p[(size_t)LL*DD*KB2];
static __device__ __nv_bfloat16 g_wqkv[(size_t)LL*3*NH*64*192];
static __device__ __nv_bfloat16 g_qs[(size_t)BB*NH*SPAD*192 + 128*192]; // +pad for qtile 1 over-read
static __device__ __nv_bfloat16 g_ks[(size_t)BB*NH*SPAD*192];
static __device__ __nv_bfloat16 g_vt[(size_t)BB*NH*128*VTP];            // [bh][hi/lo 64 rows][VTP]

// ================= tensor-core helpers =================
__device__ __forceinline__ uint32_t smem_u32(const void* p) {
    uint32_t a;
    asm("{ .reg .u64 t; cvta.to.shared.u64 t, %1; cvt.u32.u64 %0, t; }" : "=r"(a) : "l"(p));
    return a;
}
__device__ __forceinline__ void cp_async16(uint32_t smem, const void* g) {
    asm volatile("cp.async.cg.shared.global [%0], [%1], 16;" :: "r"(smem), "l"(g));
}
#define CP_COMMIT() asm volatile("cp.async.commit_group;" ::: "memory")
#define CP_WAIT1()  asm volatile("cp.async.wait_group 1;" ::: "memory")
#define CP_WAIT0()  asm volatile("cp.async.wait_group 0;" ::: "memory")

__device__ __forceinline__ void ldmx4(uint32_t* r, uint32_t addr) {
    asm volatile("ldmatrix.sync.aligned.m8n8.x4.shared.b16 {%0,%1,%2,%3}, [%4];"
        : "=r"(r[0]), "=r"(r[1]), "=r"(r[2]), "=r"(r[3]) : "r"(addr));
}
__device__ __forceinline__ void mma16816(float* d, const uint32_t* a, uint32_t b0, uint32_t b1) {
    asm volatile(
        "mma.sync.aligned.m16n8k16.row.col.f32.bf16.bf16.f32 "
        "{%0,%1,%2,%3}, {%4,%5,%6,%7}, {%8,%9}, {%0,%1,%2,%3};"
        : "+f"(d[0]), "+f"(d[1]), "+f"(d[2]), "+f"(d[3])
        : "r"(a[0]), "r"(a[1]), "r"(a[2]), "r"(a[3]), "r"(b0), "r"(b1));
}
__device__ __forceinline__ uint32_t pack_bf2(float x, float y) {
    __nv_bfloat162 t = __floats2bfloat162_rn(x, y);
    return *(uint32_t*)&t;
}
__device__ __forceinline__ unsigned short bfu(__nv_bfloat16 h) {
    return *(unsigned short*)&h;
}

// ---------------- patchify ----------------
__global__ void patchify_kernel(const float* __restrict__ x, float* __restrict__ patch)
{
    int m = blockIdx.x;
    int b = m / (NP*NP);
    int p = m % (NP*NP);
    int py = p / NP, px = p % NP;
    for (int i = threadIdx.x; i < IN_DIM; i += blockDim.x) {
        int c = i >> 8;
        int r = (i >> 4) & 15;
        int s = i & 15;
        size_t src = ((size_t)(b*CC + c)*IMG + (py*PS + r))*IMG + (px*PS + s);
        patch[(size_t)m*IN_DIM + i] = x[src];
    }
}

__global__ void cls_init_kernel(const float* __restrict__ cls_emb,
                                const float* __restrict__ pos,
                                float* __restrict__ resid)
{
    int b = blockIdx.x;
    for (int d = threadIdx.x; d < DD; d += blockDim.x)
        resid[(size_t)b*SS*DD + d] = cls_emb[d] + pos[d];
}

// ---------------- fp32 SGEMM (patch embed only) ----------------
__global__ void sgemm_embed_kernel(const float* __restrict__ A, const float* __restrict__ Bm,
                                   const float* __restrict__ bias, float* __restrict__ C,
                                   int M, int N, int K, const float* __restrict__ extra)
{
    __shared__ float As[8*128];
    __shared__ float Bs[8*128];

    const int tid = threadIdx.x;
    const int bx = blockIdx.x, by = blockIdx.y;
    const int tx = tid & 15, ty = tid >> 4;

    float acc[8][8];
#pragma unroll
    for (int i = 0; i < 8; i++)
#pragma unroll
        for (int j = 0; j < 8; j++) acc[i][j] = 0.f;

    const int aRow = tid >> 1;
    const int aK   = (tid & 1) * 4;
    const int bK   = tid >> 5;
    const int bCol = (tid & 31) * 4;
    const int globARow = by*128 + aRow;

    for (int k0 = 0; k0 < K; k0 += 8) {
        float4 av;
        if (globARow < M) av = *(const float4*)(A + (size_t)globARow*K + k0 + aK);
        else              av = make_float4(0.f,0.f,0.f,0.f);
        As[(aK+0)*128 + aRow] = av.x;
        As[(aK+1)*128 + aRow] = av.y;
        As[(aK+2)*128 + aRow] = av.z;
        As[(aK+3)*128 + aRow] = av.w;
        float4 bv = *(const float4*)(Bm + (size_t)(k0 + bK)*N + bx*128 + bCol);
        *(float4*)(Bs + bK*128 + bCol) = bv;
        __syncthreads();

#pragma unroll
        for (int kk = 0; kk < 8; kk++) {
            float a[8], b[8];
#pragma unroll
            for (int i = 0; i < 4; i++) {
                a[i]   = As[kk*128 + ty*4 + i];
                a[4+i] = As[kk*128 + 64 + ty*4 + i];
                b[i]   = Bs[kk*128 + tx*4 + i];
                b[4+i] = Bs[kk*128 + 64 + tx*4 + i];
            }
#pragma unroll
            for (int i = 0; i < 8; i++)
#pragma unroll
                for (int j = 0; j < 8; j++)
                    acc[i][j] += a[i]*b[j];
        }
        __syncthreads();
    }

#pragma unroll
    for (int i = 0; i < 8; i++) {
        int r = (i < 4) ? (ty*4 + i) : (64 + ty*4 + (i-4));
        int row = by*128 + r;
        if (row >= M) continue;
#pragma unroll
        for (int j = 0; j < 8; j++) {
            int cc = (j < 4) ? (tx*4 + j) : (64 + tx*4 + (j-4));
            int col = bx*128 + cc;
            float val = acc[i][j] + bias[col];
            int bb = row / (NP*NP);
            int pp = row % (NP*NP);
            int orow = bb*SS + 1 + pp;
            C[(size_t)orow*DD + col] = val + extra[(size_t)(pp+1)*DD + col];
        }
    }
}

// ---------------- weight prep: transpose + bf16 split, stacked K ----------------
__global__ void wprep_kernel(const float* __restrict__ W, __nv_bfloat16* __restrict__ Wp,
                             int K, int N)
{
    __shared__ float t[32][33];
    int l = blockIdx.z;
    const float* Wl = W + (size_t)l*K*N;
    __nv_bfloat16* Wpl = Wp + (size_t)l*N*3*K;
    int n0 = blockIdx.x*32, k0 = blockIdx.y*32;
    int tx = threadIdx.x, ty = threadIdx.y;

    t[ty][tx] = Wl[(size_t)(k0+ty)*N + n0+tx];
    __syncthreads();
    float v = t[tx][ty];
    int row = n0+ty, col = k0+tx;
    __nv_bfloat16 hi = __float2bfloat16(v);
    __nv_bfloat16 lo = __float2bfloat16(v - __bfloat162float(hi));
    __nv_bfloat16* dst = Wpl + (size_t)row*3*K;
    dst[col]       = hi;
    dst[K + col]   = hi;
    dst[2*K + col] = lo;
}

// ---------------- QKV weight prep ----------------
__global__ void qkv_prep_kernel(const float* __restrict__ Wq, const float* __restrict__ Wk,
                                const float* __restrict__ Wv, __nv_bfloat16* __restrict__ wout)
{
    int h = blockIdx.x, mat = blockIdx.y, l = blockIdx.z;
    const float* W = (mat == 0) ? Wq : (mat == 1) ? Wk : Wv;
    const float* Wl = W + (size_t)(l*NH + h)*64*64;
    __nv_bfloat16* dst = wout + (size_t)((l*3 + mat)*NH + h)*64*192;
    for (int idx = threadIdx.x; idx < 4096; idx += 256) {
        int e = idx >> 6, d = idx & 63;
        float v = Wl[e*64 + d];
        __nv_bfloat16 hi = __float2bfloat16(v);
        __nv_bfloat16 lo = __float2bfloat16(v - __bfloat162float(hi));
        dst[e*192 + d]       = hi;
        dst[e*192 + 64 + d]  = hi;
        dst[e*192 + 128 + d] = lo;
    }
}

// ---------------- LayerNorm -> split bf16 [row][hi(768)|lo(768)] ----------------
__global__ void ln_kernel(const float* __restrict__ xin, const float* __restrict__ g,
                          const float* __restrict__ bet, __nv_bfloat16* __restrict__ xs)
{
    int row = blockIdx.x;
    const float* xr = xin + (size_t)row*DD;
    int tid = threadIdx.x;
    float v0 = xr[tid], v1 = xr[tid+256], v2 = xr[tid+512];
    float s  = v0+v1+v2;
    float ss = v0*v0 + v1*v1 + v2*v2;

    __shared__ float rs[8], rss[8], smv[2];
    int lane = tid & 31, w = tid >> 5;
#pragma unroll
    for (int off = 16; off; off >>= 1) {
        s  += __shfl_xor_sync(0xffffffffu, s,  off);
        ss += __shfl_xor_sync(0xffffffffu, ss, off);
    }
    if (lane == 0) { rs[w] = s; rss[w] = ss; }
    __syncthreads();
    if (tid == 0) {
        float S = 0.f, SSq = 0.f;
#pragma unroll
        for (int i = 0; i < 8; i++) { S += rs[i]; SSq += rss[i]; }
        float mean = S * (1.f/768.f);
        float var  = SSq * (1.f/768.f) - mean*mean;
        smv[0] = mean;
        smv[1] = rsqrtf(var + 1e-5f);
    }
    __syncthreads();
    float mean = smv[0], rstd = smv[1];
#pragma unroll
    for (int ii = 0; ii < 3; ii++) {
        int i = tid + ii*256;
        float vv = (ii==0)?v0:(ii==1)?v1:v2;
        float y = (vv - mean)*rstd*g[i] + bet[i];
        __nv_bfloat16 hi = __float2bfloat16(y);
        __nv_bfloat16 lo = __float2bfloat16(y - __bfloat162float(hi));
        __nv_bfloat16* dst = xs + (size_t)row*KA1;
        dst[i]      = hi;
        dst[DD + i] = lo;
    }
}

// ---------------- HMMA MLP GEMM ----------------
template<int MODE>
__global__ void __launch_bounds__(256, 2)
mma_mlp_kernel(const __nv_bfloat16* __restrict__ A, const __nv_bfloat16* __restrict__ Bw,
               const float* __restrict__ bias, __nv_bfloat16* __restrict__ hs_out,
               float* __restrict__ resid, int nk, int strideA, int strideB)
{
    extern __shared__ char smc[];
    const uint32_t sbase = smem_u32(smc);
    const int tid = threadIdx.x;
    const int wid = tid >> 5, lane = tid & 31;
    const int wm = wid & 1, wn = wid >> 1;
    const int bx = blockIdx.x, by = blockIdx.y;
    const int NC = 3*nk;

    const __nv_bfloat16* Abase = A + (size_t)(by*128)*strideA;
    const __nv_bfloat16* Bbase = Bw + (size_t)(bx*128)*strideB;

    float acc[4][4][4];
#pragma unroll
    for (int i = 0; i < 4; i++)
#pragma unroll
        for (int j = 0; j < 4; j++)
#pragma unroll
            for (int q = 0; q < 4; q++) acc[i][j][q] = 0.f;

    const int lq = tid & 7;
    const int lr = tid >> 3;

    auto load_chunk = [&](int c, int p) {
        int cwrap = (c < 2*nk) ? c : (c - 2*nk);
        const __nv_bfloat16* Ap = Abase + (size_t)cwrap*64;
        const __nv_bfloat16* Bp = Bbase + (size_t)c*64;
        uint32_t sA = sbase + p*32768;
        uint32_t sB = sA + 16384;
#pragma unroll
        for (int i = 0; i < 4; i++) {
            int r = i*32 + lr;
            uint32_t off = r*128 + lq*16;
            uint32_t sw = off ^ ((off >> 3) & 0x70);
            cp_async16(sA + sw, Ap + (size_t)r*strideA + lq*8);
            cp_async16(sB + sw, Bp + (size_t)r*strideB + lq*8);
        }
        CP_COMMIT();
    };

    const int l15 = lane & 15;
    const int lks = (lane >> 4) * 16;

    load_chunk(0, 0);

    for (int c = 0; c < NC; c++) {
        int p = c & 1;
        if (c + 1 < NC) { load_chunk(c+1, (c+1)&1); CP_WAIT1(); }
        else            { CP_WAIT0(); }
        __syncthreads();

        uint32_t sA = sbase + p*32768;
        uint32_t sB = sA + 16384;
#pragma unroll
        for (int ks = 0; ks < 4; ks++) {
            uint32_t b0[4], b1[4];
            {
                uint32_t off = (wn*32 + l15)*128 + ks*32 + lks;
                ldmx4(b0, sB + (off ^ ((off >> 3) & 0x70)));
                off = (wn*32 + 16 + l15)*128 + ks*32 + lks;
                ldmx4(b1, sB + (off ^ ((off >> 3) & 0x70)));
            }
#pragma unroll
            for (int mt = 0; mt < 4; mt++) {
                uint32_t a[4];
                uint32_t off = (wm*64 + mt*16 + l15)*128 + ks*32 + lks;
                ldmx4(a, sA + (off ^ ((off >> 3) & 0x70)));
                mma16816(acc[mt][0], a, b0[0], b0[2]);
                mma16816(acc[mt][1], a, b0[1], b0[3]);
                mma16816(acc[mt][2], a, b1[0], b1[2]);
                mma16816(acc[mt][3], a, b1[1], b1[3]);
            }
        }
        __syncthreads();
    }

    const int gm0 = by*128 + wm*64 + (lane >> 2);
    const int gn0 = bx*128 + wn*32 + (lane & 3)*2;

#pragma unroll
    for (int mt = 0; mt < 4; mt++) {
#pragma unroll
        for (int nt = 0; nt < 4; nt++) {
            int col = gn0 + nt*8;
            float bi0 = bias[col], bi1 = bias[col+1];
            int r0 = gm0 + mt*16;
            int r1 = r0 + 8;
            float v00 = acc[mt][nt][0] + bi0;
            float v01 = acc[mt][nt][1] + bi1;
            float v10 = acc[mt][nt][2] + bi0;
            float v11 = acc[mt][nt][3] + bi1;
            if (MODE == 0) {
                float g00 = 0.5f*v00*(1.f + erff(v00*0.70710678118654752f));
                float g01 = 0.5f*v01*(1.f + erff(v01*0.70710678118654752f));
                float g10 = 0.5f*v10*(1.f + erff(v10*0.70710678118654752f));
                float g11 = 0.5f*v11*(1.f + erff(v11*0.70710678118654752f));
                __nv_bfloat16 h00 = __float2bfloat16(g00);
                __nv_bfloat16 h01 = __float2bfloat16(g01);
                __nv_bfloat16 h10 = __float2bfloat16(g10);
                __nv_bfloat16 h11 = __float2bfloat16(g11);
                uint32_t hi0 = (uint32_t)bfu(h00) | ((uint32_t)bfu(h01) << 16);
                uint32_t hi1 = (uint32_t)bfu(h10) | ((uint32_t)bfu(h11) << 16);
                uint32_t lo0 = pack_bf2(g00 - __bfloat162float(h00), g01 - __bfloat162float(h01));
                uint32_t lo1 = pack_bf2(g10 - __bfloat162float(h10), g11 - __bfloat162float(h11));
                if (r0 < NTOK) {
                    *(uint32_t*)(hs_out + (size_t)r0*KA2 + col)        = hi0;
                    *(uint32_t*)(hs_out + (size_t)r0*KA2 + MLPD + col) = lo0;
                }
                if (r1 < NTOK) {
                    *(uint32_t*)(hs_out + (size_t)r1*KA2 + col)        = hi1;
                    *(uint32_t*)(hs_out + (size_t)r1*KA2 + MLPD + col) = lo1;
                }
            } else {
                if (r0 < NTOK) {
                    float2* p = (float2*)(resid + (size_t)r0*DD + col);
                    float2 t = *p; t.x += v00; t.y += v01; *p = t;
                }
                if (r1 < NTOK) {
                    float2* p = (float2*)(resid + (size_t)r1*DD + col);
                    float2 t = *p; t.x += v10; t.y += v11; *p = t;
                }
            }
        }
    }
}

// ---------------- HMMA QKV projection: writes split-bf16 q_s/k_s/v_t ----------
// grid (3*NH, MPAD/128), 128 threads
__global__ void __launch_bounds__(128, 3)
qkv_mma_kernel(const __nv_bfloat16* __restrict__ xs, const __nv_bfloat16* __restrict__ wqkv,
               const float* __restrict__ bq, const float* __restrict__ bk,
               const float* __restrict__ bv,
               __nv_bfloat16* __restrict__ qsd, __nv_bfloat16* __restrict__ ksd,
               __nv_bfloat16* __restrict__ vtd)
{
    extern __shared__ char smc[];
    const uint32_t sbase = smem_u32(smc);
    const int tid = threadIdx.x;
    const int wid = tid >> 5, lane = tid & 31;
    const int hm = blockIdx.x;
    const int mat = hm / NH, h = hm % NH;
    const int by = blockIdx.y;

    const __nv_bfloat16* Wp = wqkv + (size_t)hm*64*192;
    const float* bias = (mat == 0) ? bq : (mat == 1) ? bk : bv;

    const int lq = tid & 7, lr = tid >> 3;   // lr 0..15
    // A chunks: 0 = hi (col h*64), 1 = lo (768 + h*64)
#pragma unroll
    for (int c = 0; c < 2; c++) {
        const __nv_bfloat16* Ap = xs + (c ? (DD + h*64) : (h*64));
#pragma unroll
        for (int i = 0; i < 8; i++) {
            int r = i*16 + lr;
            uint32_t off = r*128 + lq*16;
            uint32_t sw = off ^ ((off >> 3) & 0x70);
            cp_async16(sbase + c*16384 + sw, Ap + (size_t)(by*128 + r)*KA1 + lq*8);
        }
    }
#pragma unroll
    for (int c = 0; c < 3; c++) {
#pragma unroll
        for (int i = 0; i < 4; i++) {
            int r = i*16 + lr;
            uint32_t off = r*128 + lq*16;
            uint32_t sw = off ^ ((off >> 3) & 0x70);
            cp_async16(sbase + 32768 + c*8192 + sw, Wp + (size_t)r*192 + c*64 + lq*8);
        }
    }
    CP_COMMIT();
    CP_WAIT0();
    __syncthreads();

    float acc[2][8][4];
#pragma unroll
    for (int i = 0; i < 2; i++)
#pragma unroll
        for (int j = 0; j < 8; j++)
#pragma unroll
            for (int t = 0; t < 4; t++) acc[i][j][t] = 0.f;

    const int l15 = lane & 15;
    const int lks = (lane >> 4) * 16;
    const int m0 = wid*32;

#pragma unroll
    for (int pass = 0; pass < 3; pass++) {
        uint32_t sA = sbase + ((pass == 1) ? 16384 : 0);
        uint32_t sB = sbase + 32768 + pass*8192;
#pragma unroll
        for (int ks = 0; ks < 4; ks++) {
            uint32_t b[4][4];
#pragma unroll
            for (int nb = 0; nb < 4; nb++) {
                uint32_t off = (nb*16 + l15)*128 + ks*32 + lks;
                ldmx4(b[nb], sB + (off ^ ((off >> 3) & 0x70)));
            }
#pragma unroll
            for (int mt = 0; mt < 2; mt++) {
                uint32_t a[4];
                uint32_t off = (m0 + mt*16 + l15)*128 + ks*32 + lks;
                ldmx4(a, sA + (off ^ ((off >> 3) & 0x70)));
#pragma unroll
                for (int nb = 0; nb < 4; nb++) {
                    mma16816(acc[mt][2*nb],   a, b[nb][0], b[nb][2]);
                    mma16816(acc[mt][2*nb+1], a, b[nb][1], b[nb][3]);
                }
            }
        }
    }

    // epilogue: split-bf16 writes
    const int c0 = (lane & 3)*2;
#pragma unroll
    for (int mt = 0; mt < 2; mt++) {
#pragma unroll
        for (int nt = 0; nt < 8; nt++) {
            int e = nt*8 + c0;
            float bi0 = bias[h*64 + e], bi1 = bias[h*64 + e + 1];
            int r0 = by*128 + m0 + mt*16 + (lane >> 2);
#pragma unroll
            for (int half = 0; half < 2; half++) {
                int r = r0 + half*8;
                if (r >= NTOK) continue;
                float v0 = acc[mt][nt][2*half]   + bi0;
                float v1 = acc[mt][nt][2*half+1] + bi1;
                __nv_bfloat16 h0 = __float2bfloat16(v0);
                __nv_bfloat16 h1 = __float2bfloat16(v1);
                float l0 = v0 - __bfloat162float(h0);
                float l1 = v1 - __bfloat162float(h1);
                int b = r / SS, s = r % SS;
                int bh = b*NH + h;
                if (mat == 2) {
                    __nv_bfloat16* vb = vtd + (size_t)bh*128*VTP;
                    vb[(size_t)e*VTP + s]          = h0;
                    vb[(size_t)(e+1)*VTP + s]      = h1;
                    vb[(size_t)(64+e)*VTP + s]     = __float2bfloat16(l0);
                    vb[(size_t)(64+e+1)*VTP + s]   = __float2bfloat16(l1);
                } else {
                    uint32_t hi = (uint32_t)bfu(h0) | ((uint32_t)bfu(h1) << 16);
                    uint32_t lo = pack_bf2(l0, l1);
                    __nv_bfloat16* base = (mat == 0 ? qsd : ksd) + ((size_t)bh*SPAD + s)*192;
                    if (mat == 0) {
                        *(uint32_t*)(base + e)       = hi;
                        *(uint32_t*)(base + 64 + e)  = lo;
                        *(uint32_t*)(base + 128 + e) = hi;
                    } else {
                        *(uint32_t*)(base + e)       = hi;
                        *(uint32_t*)(base + 64 + e)  = hi;
                        *(uint32_t*)(base + 128 + e) = lo;
                    }
                }
            }
        }
    }
}

// ---------------- HMMA fused attention (FA2-style, register softmax) ----------
// grid (2, BB*NH), 256 threads (8 warps x 16 query rows)
__global__ void __launch_bounds__(256, 1)
attn_mma_kernel(const __nv_bfloat16* __restrict__ qsd, const __nv_bfloat16* __restrict__ ksd,
                const __nv_bfloat16* __restrict__ vtd, float* __restrict__ resid)
{
    extern __shared__ char smc[];
    const uint32_t sbase = smem_u32(smc);
    const uint32_t sQ = sbase;                 // 128 rows x 384B swizzled
    const uint32_t sK = sbase + 49152;         // 208 rows x 384B swizzled
    const uint32_t sV = sbase + 129024;        // 128 rows x 464B (no swizzle)

    const int tid = threadIdx.x;
    const int wid = tid >> 5, lane = tid & 31;
    const int qt = blockIdx.x, bh = blockIdx.y;
    const int b = bh / NH, h = bh % NH;

    const __nv_bfloat16* Qg = qsd + ((size_t)bh*SPAD + (size_t)qt*128)*192;
    const __nv_bfloat16* Kg = ksd + (size_t)bh*SPAD*192;
    const __nv_bfloat16* Vg = vtd + (size_t)bh*128*VTP;

    // group 0: Q + K
    for (int i = tid; i < 128*24; i += 256) {
        int r = i / 24, c = i % 24;
        uint32_t off = r*384 + c*16;
        cp_async16(sQ + (off ^ ((off >> 3) & 0x70)), Qg + (size_t)r*192 + c*8);
    }
    for (int i = tid; i < SPAD*24; i += 256) {
        int r = i / 24, c = i % 24;
        uint32_t off = r*384 + c*16;
        cp_async16(sK + (off ^ ((off >> 3) & 0x70)), Kg + (size_t)r*192 + c*8);
    }
    CP_COMMIT();
    // group 1: V^T
    for (int i = tid; i < 128*29; i += 256) {
        int r = i / 29, c = i % 29;
        cp_async16(sV + r*464 + c*16, Vg + (size_t)r*VTP + c*8);
    }
    CP_COMMIT();
    CP_WAIT1();
    __syncthreads();

    // ---- scores S = Q'K'^T (stacked K=192) ----
    float s[26][4];
#pragma unroll
    for (int t = 0; t < 26; t++)
#pragma unroll
        for (int e = 0; e < 4; e++) s[t][e] = 0.f;

    const int l15 = lane & 15;
    const int lks = (lane >> 4) * 16;
    const int m0 = wid * 16;

#pragma unroll 1
    for (int kc = 0; kc < 12; kc++) {
        uint32_t a[4];
        uint32_t off = (m0 + l15)*384 + kc*32 + lks;
        ldmx4(a, sQ + (off ^ ((off >> 3) & 0x70)));
#pragma unroll
        for (int nb = 0; nb < 13; nb++) {
            uint32_t bb[4];
            off = (nb*16 + l15)*384 + kc*32 + lks;
            ldmx4(bb, sK + (off ^ ((off >> 3) & 0x70)));
            mma16816(s[2*nb],   a, bb[0], bb[2]);
            mma16816(s[2*nb+1], a, bb[1], bb[3]);
        }
    }

    // ---- register softmax (rows r = lane>>2 and r+8, cols 2(lane&3)+{0,1}) ----
    const int c0 = 2*(lane & 3);
    float mx0 = -1e30f, mx1 = -1e30f;
#pragma unroll
    for (int t = 0; t < 26; t++) {
        int j0 = t*8 + c0;
        float v0 = (j0   < SS) ? s[t][0]*0.125f : -1e30f;
        float v1 = (j0+1 < SS) ? s[t][1]*0.125f : -1e30f;
        float v2 = (j0   < SS) ? s[t][2]*0.125f : -1e30f;
        float v3 = (j0+1 < SS) ? s[t][3]*0.125f : -1e30f;
        s[t][0] = v0; s[t][1] = v1; s[t][2] = v2; s[t][3] = v3;
        mx0 = fmaxf(mx0, fmaxf(v0, v1));
        mx1 = fmaxf(mx1, fmaxf(v2, v3));
    }
    mx0 = fmaxf(mx0, __shfl_xor_sync(0xffffffffu, mx0, 1));
    mx0 = fmaxf(mx0, __shfl_xor_sync(0xffffffffu, mx0, 2));
    mx1 = fmaxf(mx1, __shfl_xor_sync(0xffffffffu, mx1, 1));
    mx1 = fmaxf(mx1, __shfl_xor_sync(0xffffffffu, mx1, 2));

    float sum0 = 0.f, sum1 = 0.f;
#pragma unroll
    for (int t = 0; t < 26; t++) {
        float p0 = __expf(s[t][0] - mx0);
        float p1 = __expf(s[t][1] - mx0);
        float p2 = __expf(s[t][2] - mx1);
        float p3 = __expf(s[t][3] - mx1);
        s[t][0] = p0; s[t][1] = p1; s[t][2] = p2; s[t][3] = p3;
        sum0 += p0 + p1;
        sum1 += p2 + p3;
    }
    sum0 += __shfl_xor_sync(0xffffffffu, sum0, 1);
    sum0 += __shfl_xor_sync(0xffffffffu, sum0, 2);
    sum1 += __shfl_xor_sync(0xffffffffu, sum1, 1);
    sum1 += __shfl_xor_sync(0xffffffffu, sum1, 2);
    float inv0 = 1.f / sum0, inv1 = 1.f / sum1;

    CP_WAIT0();
    __syncthreads();

    // ---- O = Ph*Vh + Pl*Vh + Ph*Vl ----
    float o[8][4];
#pragma unroll
    for (int t = 0; t < 8; t++)
#pragma unroll
        for (int e = 0; e < 4; e++) o[t][e] = 0.f;

#pragma unroll 1
    for (int kt = 0; kt < 13; kt++) {
        uint32_t ah[4], al[4];
        {
            float p00 = s[2*kt][0],   p01 = s[2*kt][1],   p02 = s[2*kt][2],   p03 = s[2*kt][3];
            float p10 = s[2*kt+1][0], p11 = s[2*kt+1][1], p12 = s[2*kt+1][2], p13 = s[2*kt+1][3];
            __nv_bfloat16 h00 = __float2bfloat16(p00), h01 = __float2bfloat16(p01);
            __nv_bfloat16 h02 = __float2bfloat16(p02), h03 = __float2bfloat16(p03);
            __nv_bfloat16 h10 = __float2bfloat16(p10), h11 = __float2bfloat16(p11);
            __nv_bfloat16 h12 = __float2bfloat16(p12), h13 = __float2bfloat16(p13);
            ah[0] = (uint32_t)bfu(h00) | ((uint32_t)bfu(h01) << 16);
            ah[1] = (uint32_t)bfu(h02) | ((uint32_t)bfu(h03) << 16);
            ah[2] = (uint32_t)bfu(h10) | ((uint32_t)bfu(h11) << 16);
            ah[3] = (uint32_t)bfu(h12) | ((uint32_t)bfu(h13) << 16);
            al[0] = pack_bf2(p00 - __bfloat162float(h00), p01 - __bfloat162float(h01));
            al[1] = pack_bf2(p02 - __bfloat162float(h02), p03 - __bfloat162float(h03));
            al[2] = pack_bf2(p10 - __bfloat162float(h10), p11 - __bfloat162float(h11));
            al[3] = pack_bf2(p12 - __bfloat162float(h12), p13 - __bfloat162float(h13));
        }
#pragma unroll
        for (int nb = 0; nb < 4; nb++) {
            uint32_t bh_[4], bl_[4];
            ldmx4(bh_, sV + (nb*16 + l15)*464 + kt*32 + lks);
            ldmx4(bl_, sV + (64 + nb*16 + l15)*464 + kt*32 + lks);
            mma16816(o[2*nb],   ah, bh_[0], bh_[2]);
            mma16816(o[2*nb+1], ah, bh_[1], bh_[3]);
            mma16816(o[2*nb],   al, bh_[0], bh_[2]);
            mma16816(o[2*nb+1], al, bh_[1], bh_[3]);
            mma16816(o[2*nb],   ah, bl_[0], bl_[2]);
            mma16816(o[2*nb+1], ah, bl_[1], bl_[3]);
        }
    }

    // ---- epilogue: resid += O / sum ----
    const int r0 = qt*128 + m0 + (lane >> 2);
    const int r1 = r0 + 8;
#pragma unroll
    for (int nb = 0; nb < 8; nb++) {
        int col = h*64 + nb*8 + c0;
        if (r0 < SS) {
            float2* p = (float2*)(resid + ((size_t)(b*SS + r0))*DD + col);
            float2 t = *p;
            t.x += o[nb][0]*inv0;
            t.y += o[nb][1]*inv0;
            *p = t;
        }
        if (r1 < SS) {
            float2* p = (float2*)(resid + ((size_t)(b*SS + r1))*DD + col);
            float2 t = *p;
            t.x += o[nb][2]*inv1;
            t.y += o[nb][3]*inv1;
            *p = t;
        }
    }
}

// ---------------- classifier head ----------------
__global__ void head_kernel(const float* __restrict__ resid, const float* __restrict__ Wc,
                            const float* __restrict__ bc, float* __restrict__ out)
{
    __shared__ float sx[768];
    __shared__ float logit[1000];
    __shared__ float red[8];
    __shared__ float bscalar;

    int b = blockIdx.x;
    int tid = threadIdx.x;
    int lane = tid & 31, w = tid >> 5;

    for (int i = tid; i < 768; i += 256) sx[i] = resid[(size_t)b*SS*DD + i];
    __syncthreads();

    for (int o = tid; o < OUTC; o += 256) {
        float acc = bc[o];
        for (int kk = 0; kk < 768; kk++) acc += sx[kk]*Wc[(size_t)kk*OUTC + o];
        logit[o] = acc;
    }
    __syncthreads();

    float m = -1e30f;
    for (int o = tid; o < OUTC; o += 256) m = fmaxf(m, logit[o]);
#pragma unroll
    for (int off = 16; off; off >>= 1) m = fmaxf(m, __shfl_xor_sync(0xffffffffu, m, off));
    if (lane == 0) red[w] = m;
    __syncthreads();
    if (tid == 0) {
        float mm = red[0];
#pragma unroll
        for (int i = 1; i < 8; i++) mm = fmaxf(mm, red[i]);
        bscalar = mm;
    }
    __syncthreads();
    m = bscalar;

    float s = 0.f;
    for (int o = tid; o < OUTC; o += 256) {
        float e = __expf(logit[o] - m);
        logit[o] = e;
        s += e;
    }
#pragma unroll
    for (int off = 16; off; off >>= 1) s += __shfl_xor_sync(0xffffffffu, s, off);
    if (lane == 0) red[w] = s;
    __syncthreads();
    if (tid == 0) {
        float ssum = 0.f;
#pragma unroll
        for (int i = 0; i < 8; i++) ssum += red[i];
        bscalar = 1.f / ssum;
    }
    __syncthreads();
    float invs = bscalar;
    for (int o = tid; o < OUTC; o += 256)
        out[(size_t)b*OUTC + o] = logit[o] * invs;
}

// ---------------- launcher ----------------
extern "C" void kernel_launch(void* const* d_in, const int* in_sizes, int n_in,
                              void* d_out, int out_size)
{
    const float* x       = (const float*)d_in[0];
    const float* cls_emb = (const float*)d_in[1];
    const float* pos     = (const float*)d_in[2];
    const float* Wmap    = (const float*)d_in[3];
    const float* bmap    = (const float*)d_in[4];
    const float* ln1_g   = (const float*)d_in[5];
    const float* ln1_b   = (const float*)d_in[6];
    const float* Wq      = (const float*)d_in[7];
    const float* bq      = (const float*)d_in[8];
    const float* Wk      = (const float*)d_in[9];
    const float* bk      = (const float*)d_in[10];
    const float* Wv      = (const float*)d_in[11];
    const float* bv      = (const float*)d_in[12];
    const float* ln2_g   = (const float*)d_in[13];
    const float* ln2_b   = (const float*)d_in[14];
    const float* W1      = (const float*)d_in[15];
    const float* b1      = (const float*)d_in[16];
    const float* W2      = (const float*)d_in[17];
    const float* b2      = (const float*)d_in[18];
    const float* Wc      = (const float*)d_in[19];
    const float* bc      = (const float*)d_in[20];
    float* out = (float*)d_out;

    float *resid, *patch;
    __nv_bfloat16 *xs, *hs, *w1p, *w2p, *wqkv, *qsd, *ksd, *vtd;
    cudaGetSymbolAddress((void**)&resid, g_resid);
    cudaGetSymbolAddress((void**)&patch, g_patch);
    cudaGetSymbolAddress((void**)&xs,    g_xs);
    cudaGetSymbolAddress((void**)&hs,    g_hs);
    cudaGetSymbolAddress((void**)&w1p,   g_w1p);
    cudaGetSymbolAddress((void**)&w2p,   g_w2p);
    cudaGetSymbolAddress((void**)&wqkv,  g_wqkv);
    cudaGetSymbolAddress((void**)&qsd,   g_qs);
    cudaGetSymbolAddress((void**)&ksd,   g_ks);
    cudaGetSymbolAddress((void**)&vtd,   g_vt);

    const int MMA_SMEM  = 65536;
    const int QKV_SMEM  = 2*16384 + 3*8192;   // 57,344 B
    const int ATTN_SMEM = 49152 + SPAD*384 + 128*464; // 49152+79872+59392 = 188,416 B
    cudaFuncSetAttribute(mma_mlp_kernel<0>, cudaFuncAttributeMaxDynamicSharedMemorySize, MMA_SMEM);
    cudaFuncSetAttribute(mma_mlp_kernel<1>, cudaFuncAttributeMaxDynamicSharedMemorySize, MMA_SMEM);
    cudaFuncSetAttribute(qkv_mma_kernel, cudaFuncAttributeMaxDynamicSharedMemorySize, QKV_SMEM);
    cudaFuncSetAttribute(attn_mma_kernel, cudaFuncAttributeMaxDynamicSharedMemorySize, ATTN_SMEM);

    // weight prep
    wprep_kernel<<<dim3(MLPD/32, DD/32, LL), dim3(32,32)>>>(W1, w1p, DD, MLPD);
    wprep_kernel<<<dim3(DD/32, MLPD/32, LL), dim3(32,32)>>>(W2, w2p, MLPD, DD);
    qkv_prep_kernel<<<dim3(NH, 3, LL), 256>>>(Wq, Wk, Wv, wqkv);

    // patch embed + positional
    patchify_kernel<<<NPATCH, 256>>>(x, patch);
    sgemm_embed_kernel<<<dim3(DD/128, NPATCH/128), 256>>>(patch, Wmap, bmap, resid,
                                                          NPATCH, DD, IN_DIM, pos);
    cls_init_kernel<<<BB, 256>>>(cls_emb, pos, resid);

    for (int l = 0; l < LL; l++) {
        ln_kernel<<<NTOK, 256>>>(resid, ln1_g + (size_t)l*DD, ln1_b + (size_t)l*DD, xs);
        qkv_mma_kernel<<<dim3(3*NH, MPAD/128), 128, QKV_SMEM>>>(
            xs, wqkv + (size_t)l*3*NH*64*192,
            bq + (size_t)l*NH*DH, bk + (size_t)l*NH*DH, bv + (size_t)l*NH*DH,
            qsd, ksd, vtd);
        attn_mma_kernel<<<dim3(2, BB*NH), 256, ATTN_SMEM>>>(qsd, ksd, vtd, resid);

        ln_kernel<<<NTOK, 256>>>(resid, ln2_g + (size_t)l*DD, ln2_b + (size_t)l*DD, xs);
        mma_mlp_kernel<0><<<dim3(MLPD/128, MPAD/128), 256, MMA_SMEM>>>(
            xs, w1p + (size_t)l*MLPD*KB1, b1 + (size_t)l*MLPD, hs, nullptr, 12, KA1, KB1);
        mma_mlp_kernel<1><<<dim3(DD/128, MPAD/128), 256, MMA_SMEM>>>(
            hs, w2p + (size_t)l*DD*KB2, b2 + (size_t)l*DD, nullptr, resid, 48, KA2, KB2);
    }

    head_kernel<<<BB, 256>>>(resid, Wc, bc, out);
}